// round 10
// baseline (speedup 1.0000x reference)
#include <cuda_runtime.h>
#include <cuda_bf16.h>
#include <math.h>
#include <stdint.h>

// Problem constants
#define BATCH 4
#define DIM   256
#define C3    192
#define C1    64
#define HEADS 8
#define HD    32
#define HW    16384   // 128*128
#define IMG   128

// ---------------------------------------------------------------------------
// Device scratch
// ---------------------------------------------------------------------------
__device__ float g_wq [BATCH * DIM * C3];        // tf32 bits
__device__ float g_wkv[BATCH * 2*DIM * C1];      // tf32 bits
__device__ float g_tq [BATCH * DIM * HW];        // q pre-dwconv (fp32)
__device__ float g_tkv[BATCH * 2*DIM * HW];      // kv pre-dwconv (fp32)
__device__ float g_v  [BATCH * DIM * HW];        // v post-dwconv (tf32 bits)
__device__ float g_nq [BATCH * DIM];
__device__ float g_nk [BATCH * DIM];
__device__ float g_G  [BATCH * HEADS * HD * HD];
__device__ float g_Wc [BATCH * DIM * DIM];       // tf32 bits

// ---------------------------------------------------------------------------
// Helpers
// ---------------------------------------------------------------------------
__device__ __forceinline__ uint32_t smem_u32(const void* p) {
    uint32_t a;
    asm("{ .reg .u64 t; cvta.to.shared.u64 t, %1; cvt.u32.u64 %0, t; }" : "=r"(a) : "l"(p));
    return a;
}
__device__ __forceinline__ uint32_t f2tf(float x) {
    uint32_t r; asm("cvt.rna.tf32.f32 %0, %1;" : "=r"(r) : "f"(x)); return r;
}
__device__ __forceinline__ float f2tff(float x) {
    return __uint_as_float(f2tf(x));
}
#define CPA16(dst, src) asm volatile("cp.async.cg.shared.global [%0], [%1], 16;" :: "r"(dst), "l"(src) : "memory")
#define CPA_COMMIT()    asm volatile("cp.async.commit_group;" ::: "memory")
#define CPA_WAIT(n)     asm volatile("cp.async.wait_group %0;" :: "n"(n) : "memory")

__device__ __forceinline__ void mma_tf32(float* c, const uint32_t* a, const uint32_t* b) {
    asm volatile(
        "mma.sync.aligned.m16n8k8.row.col.f32.tf32.tf32.f32 "
        "{%0,%1,%2,%3}, {%4,%5,%6,%7}, {%8,%9}, {%0,%1,%2,%3};"
        : "+f"(c[0]), "+f"(c[1]), "+f"(c[2]), "+f"(c[3])
        : "r"(a[0]), "r"(a[1]), "r"(a[2]), "r"(a[3]), "r"(b[0]), "r"(b[1]));
}

// GEMM SMEM layout constants (bytes)
#define A_PITCH  36
#define B_PITCH  136
#define A_BYTES  (128 * A_PITCH * 4)
#define B_BYTES  (32 * B_PITCH * 4)
#define STAGE_BYTES (A_BYTES + B_BYTES)
#define SMEM_TOTAL (2 * STAGE_BYTES)
#define C_PITCH  68

// ---------------------------------------------------------------------------
// FiLM folded into per-batch weights (pre-converted to tf32 bits) + zeroing
// ---------------------------------------------------------------------------
__global__ void modk_kernel(const float* __restrict__ k_v,
                            const float* __restrict__ w_kR,
                            const float* __restrict__ w_kI,
                            const float* __restrict__ w_qR,
                            const float* __restrict__ w_kvI) {
    int b = blockIdx.x;
    int t = threadIdx.x;
    __shared__ float sc[DIM];
    if (t < C3) {
        float s = 0.f;
        const float* kb = k_v + b * 256;
        for (int i = 0; i < 192; i++) s += kb[i] * w_kR[t * 192 + i];
        sc[t] = 1.f + s;
    } else {
        int o = t - C3;
        float s = 0.f;
        const float* kb = k_v + b * 256 + 192;
        for (int i = 0; i < 64; i++) s += kb[i] * w_kI[o * 64 + i];
        sc[t] = 1.f + s;
    }
    __syncthreads();
    for (int idx = t; idx < DIM * C3; idx += blockDim.x)
        g_wq[b * DIM * C3 + idx] = f2tff(w_qR[idx] * sc[idx % C3]);
    for (int idx = t; idx < 2 * DIM * C1; idx += blockDim.x)
        g_wkv[b * 2 * DIM * C1 + idx] = f2tff(w_kvI[idx] * sc[C3 + (idx & 63)]);
    for (int i = t; i < DIM; i += blockDim.x) {
        g_nq[b * DIM + i] = 0.f;
        g_nk[b * DIM + i] = 0.f;
    }
    for (int i = t; i < HEADS * HD * HD; i += blockDim.x)
        g_G[b * HEADS * HD * HD + i] = 0.f;
}

// ---------------------------------------------------------------------------
// tf32 mma.sync GEMM (A always pre-converted; CONV_B converts at SMEM-fill)
// ---------------------------------------------------------------------------
template <int K, int OC, bool CONV_B>
__device__ __forceinline__ void mma_gemm_body(const float* __restrict__ W,
                                              const float* __restrict__ X,
                                              float* __restrict__ C,
                                              int x_bstride, int x_off) {
    extern __shared__ char smem[];
    const int b  = blockIdx.z;
    const int n0 = blockIdx.x * 128;
    const int o0 = blockIdx.y * 128;
    const float* Wb = W + (size_t)b * OC * K + (size_t)o0 * K;
    const float* Xb = X + (size_t)b * x_bstride + x_off + n0;
    float*       Cb = C + (size_t)b * OC * HW + (size_t)o0 * HW + n0;

    const int t = threadIdx.x;
    const int warp = t >> 5, lane = t & 31;
    const int wm = warp >> 2, wn = warp & 3;
    const int g = lane >> 2, tg = lane & 3;

    const uint32_t sbase = smem_u32(smem);
    const int am = t >> 3;
    const int a16 = (t & 7) * 16;
    const int bn16 = (t & 31) * 16;
    const int bk = t >> 5;

    float acc[4][4][4];
    #pragma unroll
    for (int i = 0; i < 4; i++)
        #pragma unroll
        for (int j = 0; j < 4; j++)
            #pragma unroll
            for (int r = 0; r < 4; r++) acc[i][j][r] = 0.f;

    constexpr int NCHUNK = K / 32;
    float4 bregs[4];

    {
        uint32_t ab = sbase;
        uint32_t bb = sbase + A_BYTES;
        #pragma unroll
        for (int i = 0; i < 4; i++) {
            int m = am + 32 * i;
            CPA16(ab + m * (A_PITCH * 4) + a16, Wb + (size_t)m * K + (a16 >> 2));
        }
        if (CONV_B) {
            #pragma unroll
            for (int i = 0; i < 4; i++)
                bregs[i] = *reinterpret_cast<const float4*>(Xb + (size_t)(bk + 8 * i) * HW + (bn16 >> 2));
            CPA_COMMIT();
            #pragma unroll
            for (int i = 0; i < 4; i++) {
                float4 v = bregs[i];
                v.x = f2tff(v.x); v.y = f2tff(v.y); v.z = f2tff(v.z); v.w = f2tff(v.w);
                *reinterpret_cast<float4*>(smem + A_BYTES + (bk + 8 * i) * (B_PITCH * 4) + bn16) = v;
            }
        } else {
            #pragma unroll
            for (int i = 0; i < 4; i++) {
                int kk = bk + 8 * i;
                CPA16(bb + kk * (B_PITCH * 4) + bn16, Xb + (size_t)kk * HW + (bn16 >> 2));
            }
            CPA_COMMIT();
        }
        CPA_WAIT(0);
        __syncthreads();
    }

    #pragma unroll 1
    for (int c = 0; c < NCHUNK; c++) {
        const bool more = (c + 1 < NCHUNK);
        if (more) {
            int s = (c + 1) & 1;
            int k0 = (c + 1) * 32;
            uint32_t ab = sbase + s * STAGE_BYTES;
            uint32_t bb = ab + A_BYTES;
            if (CONV_B) {
                #pragma unroll
                for (int i = 0; i < 4; i++)
                    bregs[i] = *reinterpret_cast<const float4*>(Xb + (size_t)(k0 + bk + 8 * i) * HW + (bn16 >> 2));
            } else {
                #pragma unroll
                for (int i = 0; i < 4; i++) {
                    int kk = bk + 8 * i;
                    CPA16(bb + kk * (B_PITCH * 4) + bn16, Xb + (size_t)(k0 + kk) * HW + (bn16 >> 2));
                }
            }
            #pragma unroll
            for (int i = 0; i < 4; i++) {
                int m = am + 32 * i;
                CPA16(ab + m * (A_PITCH * 4) + a16, Wb + (size_t)m * K + k0 + (a16 >> 2));
            }
            CPA_COMMIT();
        }

        const uint32_t* Asu = reinterpret_cast<const uint32_t*>(smem + (c & 1) * STAGE_BYTES);
        const uint32_t* Bsu = reinterpret_cast<const uint32_t*>(smem + (c & 1) * STAGE_BYTES + A_BYTES);

        #pragma unroll
        for (int ks = 0; ks < 4; ks++) {
            uint32_t afr[4][4];
            #pragma unroll
            for (int mf = 0; mf < 4; mf++) {
                int m = wm * 64 + mf * 16 + g;
                int k = ks * 8 + tg;
                afr[mf][0] = Asu[m * A_PITCH + k];
                afr[mf][1] = Asu[(m + 8) * A_PITCH + k];
                afr[mf][2] = Asu[m * A_PITCH + k + 4];
                afr[mf][3] = Asu[(m + 8) * A_PITCH + k + 4];
            }
            uint32_t bfr[4][2];
            #pragma unroll
            for (int nf = 0; nf < 4; nf++) {
                int n = wn * 32 + nf * 8 + g;
                int k = ks * 8 + tg;
                bfr[nf][0] = Bsu[k * B_PITCH + n];
                bfr[nf][1] = Bsu[(k + 4) * B_PITCH + n];
            }
            #pragma unroll
            for (int mf = 0; mf < 4; mf++)
                #pragma unroll
                for (int nf = 0; nf < 4; nf++)
                    mma_tf32(acc[mf][nf], afr[mf], bfr[nf]);
        }

        if (more) {
            if (CONV_B) {
                int s = (c + 1) & 1;
                #pragma unroll
                for (int i = 0; i < 4; i++) {
                    float4 v = bregs[i];
                    v.x = f2tff(v.x); v.y = f2tff(v.y); v.z = f2tff(v.z); v.w = f2tff(v.w);
                    *reinterpret_cast<float4*>(smem + s * STAGE_BYTES + A_BYTES +
                                               (bk + 8 * i) * (B_PITCH * 4) + bn16) = v;
                }
            }
            CPA_WAIT(0);
        }
        __syncthreads();
    }

    float* Cs = reinterpret_cast<float*>(smem);
    #pragma unroll
    for (int half = 0; half < 2; half++) {
        if ((wn >> 1) == half) {
            int cb = wn * 32 - half * 64;
            #pragma unroll
            for (int mf = 0; mf < 4; mf++) {
                #pragma unroll
                for (int nf = 0; nf < 4; nf++) {
                    int row = wm * 64 + mf * 16 + g;
                    int col = cb + nf * 8 + tg * 2;
                    *reinterpret_cast<float2*>(&Cs[row * C_PITCH + col]) =
                        make_float2(acc[mf][nf][0], acc[mf][nf][1]);
                    *reinterpret_cast<float2*>(&Cs[(row + 8) * C_PITCH + col]) =
                        make_float2(acc[mf][nf][2], acc[mf][nf][3]);
                }
            }
        }
        __syncthreads();
        #pragma unroll
        for (int i = 0; i < 8; i++) {
            int r = (t >> 4) + 16 * i;
            int col = (t & 15) * 4;
            float4 v = *reinterpret_cast<const float4*>(&Cs[r * C_PITCH + col]);
            *reinterpret_cast<float4*>(&Cb[(size_t)r * HW + half * 64 + col]) = v;
        }
        __syncthreads();
    }
}

__global__ void __launch_bounds__(256, 3) mma_q_kernel(const float* __restrict__ x) {
    mma_gemm_body<C3, DIM, true>(g_wq, x, g_tq, DIM * HW, 0);
}
__global__ void __launch_bounds__(256, 3) mma_kv_kernel(const float* __restrict__ x) {
    mma_gemm_body<C1, 2 * DIM, true>(g_wkv, x, g_tkv, DIM * HW, C3 * HW);
}
__global__ void __launch_bounds__(256, 3) mma_o_kernel(float* __restrict__ out) {
    mma_gemm_body<DIM, DIM, false>(g_Wc, g_v, out, DIM * HW, 0);
}

// ---------------------------------------------------------------------------
// Fused: dwconv(q) + dwconv(k) + L2 sum-of-squares + 32x32 Gram per head.
// One image row per chunk; 4 rows per block. SMEM ~40 KB -> 4 blocks/SM.
// ---------------------------------------------------------------------------
#define FP      132
#define QC_OFF  0
#define KC_OFF  (32 * FP)            // 4224
#define SG_OFF  (2 * 32 * FP)        // 8448
#define SN_OFF  (SG_OFF + 1024)      // 9472
#define WS_OFF  (SN_OFF + 64)        // 9536
#define FUSED_SMEM_BYTES ((WS_OFF + 576) * 4)   // 40448

__global__ void __launch_bounds__(256, 4) fused_qk_gram_kernel(
        const float* __restrict__ w_qdw, const float* __restrict__ w_kvdw) {
    extern __shared__ float sf[];
    const int h = blockIdx.y, b = blockIdx.z;
    const int t = threadIdx.x;
    const int w = t >> 5, lane = t & 31;
    const int yb = blockIdx.x * 4;

    const float* qbase = g_tq  + ((size_t)b * DIM     + h * HD) * HW;
    const float* kbase = g_tkv + ((size_t)b * 2 * DIM + h * HD) * HW;

    for (int i = t; i < 1024 + 64; i += 256) sf[SG_OFF + i] = 0.f;
    for (int i = t; i < 2 * HD * 9; i += 256) {
        int tens = i / 288, r = i % 288;
        sf[WS_OFF + i] = (tens ? w_kvdw : w_qdw)[(h * HD) * 9 + r];
    }
    __syncthreads();

    float acc[4][4] = {};
    const int seg = t >> 6, tt = t & 63, i4 = tt >> 3, j4 = tt & 7;

    #pragma unroll 1
    for (int ch = 0; ch < 4; ch++) {
        const int oy = yb + ch;
        // ---- conv: 64 tasks (2 tensors x 32 ch), one row each, 8 per warp
        #pragma unroll 1
        for (int i = 0; i < 8; i++) {
            int task = w + 8 * i;
            int tens = task >> 5;
            int c = task & 31;
            const float* plane = (tens ? kbase : qbase) + (size_t)c * HW;
            float4 r0 = (oy > 0)
                ? *reinterpret_cast<const float4*>(plane + (size_t)(oy - 1) * IMG + lane * 4)
                : make_float4(0.f, 0.f, 0.f, 0.f);
            float4 r1 = *reinterpret_cast<const float4*>(plane + (size_t)oy * IMG + lane * 4);
            float4 r2 = (oy < IMG - 1)
                ? *reinterpret_cast<const float4*>(plane + (size_t)(oy + 1) * IMG + lane * 4)
                : make_float4(0.f, 0.f, 0.f, 0.f);
            float l0 = __shfl_up_sync(0xffffffffu, r0.w, 1);
            float l1 = __shfl_up_sync(0xffffffffu, r1.w, 1);
            float l2 = __shfl_up_sync(0xffffffffu, r2.w, 1);
            float h0 = __shfl_down_sync(0xffffffffu, r0.x, 1);
            float h1 = __shfl_down_sync(0xffffffffu, r1.x, 1);
            float h2 = __shfl_down_sync(0xffffffffu, r2.x, 1);
            if (lane == 0)  { l0 = 0.f; l1 = 0.f; l2 = 0.f; }
            if (lane == 31) { h0 = 0.f; h1 = 0.f; h2 = 0.f; }
            const float* w9 = sf + WS_OFF + tens * 288 + c * 9;
            float wa = w9[0], wb = w9[1], wc = w9[2];
            float wd = w9[3], we = w9[4], wf = w9[5];
            float wg = w9[6], wh = w9[7], wi = w9[8];
            float o0 = wa*l0   + wb*r0.x + wc*r0.y + wd*l1   + we*r1.x + wf*r1.y + wg*l2   + wh*r2.x + wi*r2.y;
            float o1 = wa*r0.x + wb*r0.y + wc*r0.z + wd*r1.x + we*r1.y + wf*r1.z + wg*r2.x + wh*r2.y + wi*r2.z;
            float o2 = wa*r0.y + wb*r0.z + wc*r0.w + wd*r1.y + we*r1.z + wf*r1.w + wg*r2.y + wh*r2.z + wi*r2.w;
            float o3 = wa*r0.z + wb*r0.w + wc*h0   + wd*r1.z + we*r1.w + wf*h1   + wg*r2.z + wh*r2.w + wi*h2;
            *reinterpret_cast<float4*>(sf + (tens ? KC_OFF : QC_OFF) + c * FP + lane * 4) =
                make_float4(o0, o1, o2, o3);
            float ssq = o0*o0 + o1*o1 + o2*o2 + o3*o3;
            #pragma unroll
            for (int off = 16; off > 0; off >>= 1)
                ssq += __shfl_down_sync(0xffffffffu, ssq, off);
            if (lane == 0) atomicAdd(&sf[SN_OFF + tens * HD + c], ssq);
        }
        __syncthreads();
        // ---- gram over this row (128 px), each seg handles 32 px
        const float* QCp = sf + QC_OFF;
        const float* KCp = sf + KC_OFF;
        #pragma unroll 2
        for (int jj = seg * 32; jj < seg * 32 + 32; jj += 4) {
            float4 q4[4], k4[4];
            #pragma unroll
            for (int r = 0; r < 4; r++)
                q4[r] = *reinterpret_cast<const float4*>(&QCp[(i4 + 8 * r) * FP + jj]);
            #pragma unroll
            for (int s = 0; s < 4; s++)
                k4[s] = *reinterpret_cast<const float4*>(&KCp[(j4 + 8 * s) * FP + jj]);
            #pragma unroll
            for (int r = 0; r < 4; r++)
                #pragma unroll
                for (int s = 0; s < 4; s++)
                    acc[r][s] += q4[r].x * k4[s].x + q4[r].y * k4[s].y
                               + q4[r].z * k4[s].z + q4[r].w * k4[s].w;
        }
        __syncthreads();
    }
    #pragma unroll
    for (int r = 0; r < 4; r++)
        #pragma unroll
        for (int s = 0; s < 4; s++)
            atomicAdd(&sf[SG_OFF + (i4 + 8 * r) * HD + (j4 + 8 * s)], acc[r][s]);
    __syncthreads();
    float* Gp = g_G + (size_t)(b * HEADS + h) * HD * HD;
    for (int e = t; e < HD * HD; e += 256) atomicAdd(&Gp[e], sf[SG_OFF + e]);
    if (t < 64) {
        float* np = (t < HD) ? g_nq : g_nk;
        atomicAdd(&np[b * DIM + h * HD + (t & 31)], sf[SN_OFF + t]);
    }
}

// ---------------------------------------------------------------------------
// Depthwise 3x3 conv for V (stores tf32 bits for the o-GEMM)
// ---------------------------------------------------------------------------
__global__ void __launch_bounds__(256) dwv_kernel(const float* __restrict__ w9) {
    int b = blockIdx.z, c = blockIdx.y, chunk = blockIdx.x;
    const float* ip = g_tkv + ((size_t)b * 2 * DIM + DIM + c) * HW;
    float*       op = g_v   + ((size_t)b * DIM + c) * HW;
    float wv[9];
    #pragma unroll
    for (int i = 0; i < 9; i++) wv[i] = w9[(DIM + c) * 9 + i];
    #pragma unroll
    for (int it = 0; it < 8; it++) {
        int p = chunk * 2048 + it * 256 + threadIdx.x;
        int y = p >> 7, x = p & 127;
        float s = 0.f;
        #pragma unroll
        for (int dy = -1; dy <= 1; dy++) {
            int yy = y + dy;
            if ((unsigned)yy < (unsigned)IMG) {
                const float* rp = ip + yy * IMG;
                #pragma unroll
                for (int dx = -1; dx <= 1; dx++) {
                    int xx = x + dx;
                    if ((unsigned)xx < (unsigned)IMG)
                        s += wv[(dy + 1) * 3 + dx + 1] * rp[xx];
                }
            }
        }
        op[p] = f2tff(s);
    }
}

// ---------------------------------------------------------------------------
// Softmax + fold attention into w_proj (stores tf32 bits)
// ---------------------------------------------------------------------------
__global__ void __launch_bounds__(256) attn_wc_kernel(const float* __restrict__ temp,
                                                      const float* __restrict__ w_proj) {
    int h = blockIdx.x, b = blockIdx.y;
    int t = threadIdx.x;
    __shared__ float As[HD][HD + 1];
    __shared__ float qn[HD], kn[HD];

    if (t < HD) {
        qn[t] = fmaxf(sqrtf(g_nq[b * DIM + h * HD + t]), 1e-12f);
        kn[t] = fmaxf(sqrtf(g_nk[b * DIM + h * HD + t]), 1e-12f);
    }
    __syncthreads();
    if (t < HD) {
        int c = t;
        float T = temp[h];
        float inq = T / qn[c];
        const float* Gp = &g_G[((size_t)(b * HEADS + h) * HD + c) * HD];
        float rowv[HD];
        float m = -1e30f;
        #pragma unroll
        for (int d = 0; d < HD; d++) {
            float v = Gp[d] * inq / kn[d];
            rowv[d] = v;
            m = fmaxf(m, v);
        }
        float ssum = 0.f;
        #pragma unroll
        for (int d = 0; d < HD; d++) { rowv[d] = expf(rowv[d] - m); ssum += rowv[d]; }
        float inv = 1.f / ssum;
        #pragma unroll
        for (int d = 0; d < HD; d++) As[c][d] = rowv[d] * inv;
    }
    __syncthreads();

    int o = t;
    float wp[HD];
    #pragma unroll
    for (int c = 0; c < HD; c++) wp[c] = w_proj[o * DIM + h * HD + c];
    #pragma unroll 4
    for (int d = 0; d < HD; d++) {
        float s = 0.f;
        #pragma unroll
        for (int c = 0; c < HD; c++) s += wp[c] * As[c][d];
        g_Wc[((size_t)b * DIM + o) * DIM + h * HD + d] = f2tff(s);
    }
}

// ---------------------------------------------------------------------------
// Launch
// ---------------------------------------------------------------------------
extern "C" void kernel_launch(void* const* d_in, const int* in_sizes, int n_in,
                              void* d_out, int out_size) {
    const float* x      = (const float*)d_in[0];
    const float* k_v    = (const float*)d_in[1];
    const float* temper = (const float*)d_in[2];
    const float* w_kR   = (const float*)d_in[3];
    const float* w_kI   = (const float*)d_in[4];
    const float* w_qR   = (const float*)d_in[5];
    const float* w_qdw  = (const float*)d_in[6];
    const float* w_kvI  = (const float*)d_in[7];
    const float* w_kvdw = (const float*)d_in[8];
    const float* w_proj = (const float*)d_in[9];
    float* out = (float*)d_out;

    cudaFuncSetAttribute(mma_q_kernel,  cudaFuncAttributeMaxDynamicSharedMemorySize, SMEM_TOTAL);
    cudaFuncSetAttribute(mma_kv_kernel, cudaFuncAttributeMaxDynamicSharedMemorySize, SMEM_TOTAL);
    cudaFuncSetAttribute(mma_o_kernel,  cudaFuncAttributeMaxDynamicSharedMemorySize, SMEM_TOTAL);
    cudaFuncSetAttribute(fused_qk_gram_kernel, cudaFuncAttributeMaxDynamicSharedMemorySize, FUSED_SMEM_BYTES);

    modk_kernel<<<BATCH, 256>>>(k_v, w_kR, w_kI, w_qR, w_kvI);
    mma_q_kernel <<<dim3(HW / 128, DIM / 128,     BATCH), 256, SMEM_TOTAL>>>(x);
    mma_kv_kernel<<<dim3(HW / 128, 2 * DIM / 128, BATCH), 256, SMEM_TOTAL>>>(x);
    fused_qk_gram_kernel<<<dim3(32, HEADS, BATCH), 256, FUSED_SMEM_BYTES>>>(w_qdw, w_kvdw);
    dwv_kernel<<<dim3(8, DIM, BATCH), 256>>>(w_kvdw);
    attn_wc_kernel<<<dim3(HEADS, BATCH), 256>>>(temper, w_proj);
    mma_o_kernel<<<dim3(HW / 128, DIM / 128, BATCH), 256, SMEM_TOTAL>>>(out);
}

// round 11
// speedup vs baseline: 1.3696x; 1.3696x over previous
#include <cuda_runtime.h>
#include <cuda_bf16.h>
#include <math.h>
#include <stdint.h>

// Problem constants
#define BATCH 4
#define DIM   256
#define C3    192
#define C1    64
#define HEADS 8
#define HD    32
#define HW    16384   // 128*128
#define IMG   128

// ---------------------------------------------------------------------------
// Device scratch
// ---------------------------------------------------------------------------
__device__ float g_wq [BATCH * DIM * C3];        // tf32 bits
__device__ float g_wkv[BATCH * 2*DIM * C1];      // tf32 bits
__device__ float g_tq [BATCH * DIM * HW];        // q pre-dwconv (fp32)
__device__ float g_tkv[BATCH * 2*DIM * HW];      // kv pre-dwconv (fp32)
__device__ float g_v  [BATCH * DIM * HW];        // v post-dwconv (tf32 bits)
__device__ float g_nq [BATCH * DIM];
__device__ float g_nk [BATCH * DIM];
__device__ float g_G  [BATCH * HEADS * HD * HD];
__device__ float g_Wc [BATCH * DIM * DIM];       // tf32 bits

// ---------------------------------------------------------------------------
// Helpers
// ---------------------------------------------------------------------------
__device__ __forceinline__ uint32_t smem_u32(const void* p) {
    uint32_t a;
    asm("{ .reg .u64 t; cvta.to.shared.u64 t, %1; cvt.u32.u64 %0, t; }" : "=r"(a) : "l"(p));
    return a;
}
__device__ __forceinline__ uint32_t f2tf(float x) {
    uint32_t r; asm("cvt.rna.tf32.f32 %0, %1;" : "=r"(r) : "f"(x)); return r;
}
__device__ __forceinline__ float f2tff(float x) {
    return __uint_as_float(f2tf(x));
}
#define CPA16(dst, src) asm volatile("cp.async.cg.shared.global [%0], [%1], 16;" :: "r"(dst), "l"(src) : "memory")
#define CPA_COMMIT()    asm volatile("cp.async.commit_group;" ::: "memory")
#define CPA_WAIT(n)     asm volatile("cp.async.wait_group %0;" :: "n"(n) : "memory")

__device__ __forceinline__ void mma_tf32(float* c, const uint32_t* a, const uint32_t* b) {
    asm volatile(
        "mma.sync.aligned.m16n8k8.row.col.f32.tf32.tf32.f32 "
        "{%0,%1,%2,%3}, {%4,%5,%6,%7}, {%8,%9}, {%0,%1,%2,%3};"
        : "+f"(c[0]), "+f"(c[1]), "+f"(c[2]), "+f"(c[3])
        : "r"(a[0]), "r"(a[1]), "r"(a[2]), "r"(a[3]), "r"(b[0]), "r"(b[1]));
}

// GEMM SMEM layout constants (bytes)
#define A_PITCH  36
#define B_PITCH  136
#define A_BYTES  (128 * A_PITCH * 4)
#define B_BYTES  (32 * B_PITCH * 4)
#define STAGE_BYTES (A_BYTES + B_BYTES)
#define SMEM_TOTAL (2 * STAGE_BYTES)
#define C_PITCH  68

// ---------------------------------------------------------------------------
// FiLM folded into per-batch weights (pre-converted to tf32 bits) + zeroing
// ---------------------------------------------------------------------------
__global__ void modk_kernel(const float* __restrict__ k_v,
                            const float* __restrict__ w_kR,
                            const float* __restrict__ w_kI,
                            const float* __restrict__ w_qR,
                            const float* __restrict__ w_kvI) {
    int b = blockIdx.x;
    int t = threadIdx.x;
    __shared__ float sc[DIM];
    if (t < C3) {
        float s = 0.f;
        const float* kb = k_v + b * 256;
        for (int i = 0; i < 192; i++) s += kb[i] * w_kR[t * 192 + i];
        sc[t] = 1.f + s;
    } else {
        int o = t - C3;
        float s = 0.f;
        const float* kb = k_v + b * 256 + 192;
        for (int i = 0; i < 64; i++) s += kb[i] * w_kI[o * 64 + i];
        sc[t] = 1.f + s;
    }
    __syncthreads();
    for (int idx = t; idx < DIM * C3; idx += blockDim.x)
        g_wq[b * DIM * C3 + idx] = f2tff(w_qR[idx] * sc[idx % C3]);
    for (int idx = t; idx < 2 * DIM * C1; idx += blockDim.x)
        g_wkv[b * 2 * DIM * C1 + idx] = f2tff(w_kvI[idx] * sc[C3 + (idx & 63)]);
    for (int i = t; i < DIM; i += blockDim.x) {
        g_nq[b * DIM + i] = 0.f;
        g_nk[b * DIM + i] = 0.f;
    }
    for (int i = t; i < HEADS * HD * HD; i += blockDim.x)
        g_G[b * HEADS * HD * HD + i] = 0.f;
}

// ---------------------------------------------------------------------------
// tf32 mma.sync GEMM (A always pre-converted; CONV_B converts at SMEM-fill)
// ---------------------------------------------------------------------------
template <int K, int OC, bool CONV_B>
__device__ __forceinline__ void mma_gemm_body(const float* __restrict__ W,
                                              const float* __restrict__ X,
                                              float* __restrict__ C,
                                              int x_bstride, int x_off) {
    extern __shared__ char smem[];
    const int b  = blockIdx.z;
    const int n0 = blockIdx.x * 128;
    const int o0 = blockIdx.y * 128;
    const float* Wb = W + (size_t)b * OC * K + (size_t)o0 * K;
    const float* Xb = X + (size_t)b * x_bstride + x_off + n0;
    float*       Cb = C + (size_t)b * OC * HW + (size_t)o0 * HW + n0;

    const int t = threadIdx.x;
    const int warp = t >> 5, lane = t & 31;
    const int wm = warp >> 2, wn = warp & 3;
    const int g = lane >> 2, tg = lane & 3;

    const uint32_t sbase = smem_u32(smem);
    const int am = t >> 3;
    const int a16 = (t & 7) * 16;
    const int bn16 = (t & 31) * 16;
    const int bk = t >> 5;

    float acc[4][4][4];
    #pragma unroll
    for (int i = 0; i < 4; i++)
        #pragma unroll
        for (int j = 0; j < 4; j++)
            #pragma unroll
            for (int r = 0; r < 4; r++) acc[i][j][r] = 0.f;

    constexpr int NCHUNK = K / 32;
    float4 bregs[4];

    {
        uint32_t ab = sbase;
        uint32_t bb = sbase + A_BYTES;
        #pragma unroll
        for (int i = 0; i < 4; i++) {
            int m = am + 32 * i;
            CPA16(ab + m * (A_PITCH * 4) + a16, Wb + (size_t)m * K + (a16 >> 2));
        }
        if (CONV_B) {
            #pragma unroll
            for (int i = 0; i < 4; i++)
                bregs[i] = *reinterpret_cast<const float4*>(Xb + (size_t)(bk + 8 * i) * HW + (bn16 >> 2));
            CPA_COMMIT();
            #pragma unroll
            for (int i = 0; i < 4; i++) {
                float4 v = bregs[i];
                v.x = f2tff(v.x); v.y = f2tff(v.y); v.z = f2tff(v.z); v.w = f2tff(v.w);
                *reinterpret_cast<float4*>(smem + A_BYTES + (bk + 8 * i) * (B_PITCH * 4) + bn16) = v;
            }
        } else {
            #pragma unroll
            for (int i = 0; i < 4; i++) {
                int kk = bk + 8 * i;
                CPA16(bb + kk * (B_PITCH * 4) + bn16, Xb + (size_t)kk * HW + (bn16 >> 2));
            }
            CPA_COMMIT();
        }
        CPA_WAIT(0);
        __syncthreads();
    }

    #pragma unroll 1
    for (int c = 0; c < NCHUNK; c++) {
        const bool more = (c + 1 < NCHUNK);
        if (more) {
            int s = (c + 1) & 1;
            int k0 = (c + 1) * 32;
            uint32_t ab = sbase + s * STAGE_BYTES;
            uint32_t bb = ab + A_BYTES;
            if (CONV_B) {
                #pragma unroll
                for (int i = 0; i < 4; i++)
                    bregs[i] = *reinterpret_cast<const float4*>(Xb + (size_t)(k0 + bk + 8 * i) * HW + (bn16 >> 2));
            } else {
                #pragma unroll
                for (int i = 0; i < 4; i++) {
                    int kk = bk + 8 * i;
                    CPA16(bb + kk * (B_PITCH * 4) + bn16, Xb + (size_t)(k0 + kk) * HW + (bn16 >> 2));
                }
            }
            #pragma unroll
            for (int i = 0; i < 4; i++) {
                int m = am + 32 * i;
                CPA16(ab + m * (A_PITCH * 4) + a16, Wb + (size_t)m * K + k0 + (a16 >> 2));
            }
            CPA_COMMIT();
        }

        const uint32_t* Asu = reinterpret_cast<const uint32_t*>(smem + (c & 1) * STAGE_BYTES);
        const uint32_t* Bsu = reinterpret_cast<const uint32_t*>(smem + (c & 1) * STAGE_BYTES + A_BYTES);

        #pragma unroll
        for (int ks = 0; ks < 4; ks++) {
            uint32_t afr[4][4];
            #pragma unroll
            for (int mf = 0; mf < 4; mf++) {
                int m = wm * 64 + mf * 16 + g;
                int k = ks * 8 + tg;
                afr[mf][0] = Asu[m * A_PITCH + k];
                afr[mf][1] = Asu[(m + 8) * A_PITCH + k];
                afr[mf][2] = Asu[m * A_PITCH + k + 4];
                afr[mf][3] = Asu[(m + 8) * A_PITCH + k + 4];
            }
            uint32_t bfr[4][2];
            #pragma unroll
            for (int nf = 0; nf < 4; nf++) {
                int n = wn * 32 + nf * 8 + g;
                int k = ks * 8 + tg;
                bfr[nf][0] = Bsu[k * B_PITCH + n];
                bfr[nf][1] = Bsu[(k + 4) * B_PITCH + n];
            }
            #pragma unroll
            for (int mf = 0; mf < 4; mf++)
                #pragma unroll
                for (int nf = 0; nf < 4; nf++)
                    mma_tf32(acc[mf][nf], afr[mf], bfr[nf]);
        }

        if (more) {
            if (CONV_B) {
                int s = (c + 1) & 1;
                #pragma unroll
                for (int i = 0; i < 4; i++) {
                    float4 v = bregs[i];
                    v.x = f2tff(v.x); v.y = f2tff(v.y); v.z = f2tff(v.z); v.w = f2tff(v.w);
                    *reinterpret_cast<float4*>(smem + s * STAGE_BYTES + A_BYTES +
                                               (bk + 8 * i) * (B_PITCH * 4) + bn16) = v;
                }
            }
            CPA_WAIT(0);
        }
        __syncthreads();
    }

    float* Cs = reinterpret_cast<float*>(smem);
    #pragma unroll
    for (int half = 0; half < 2; half++) {
        if ((wn >> 1) == half) {
            int cb = wn * 32 - half * 64;
            #pragma unroll
            for (int mf = 0; mf < 4; mf++) {
                #pragma unroll
                for (int nf = 0; nf < 4; nf++) {
                    int row = wm * 64 + mf * 16 + g;
                    int col = cb + nf * 8 + tg * 2;
                    *reinterpret_cast<float2*>(&Cs[row * C_PITCH + col]) =
                        make_float2(acc[mf][nf][0], acc[mf][nf][1]);
                    *reinterpret_cast<float2*>(&Cs[(row + 8) * C_PITCH + col]) =
                        make_float2(acc[mf][nf][2], acc[mf][nf][3]);
                }
            }
        }
        __syncthreads();
        #pragma unroll
        for (int i = 0; i < 8; i++) {
            int r = (t >> 4) + 16 * i;
            int col = (t & 15) * 4;
            float4 v = *reinterpret_cast<const float4*>(&Cs[r * C_PITCH + col]);
            *reinterpret_cast<float4*>(&Cb[(size_t)r * HW + half * 64 + col]) = v;
        }
        __syncthreads();
    }
}

__global__ void __launch_bounds__(256) mma_q_kernel(const float* __restrict__ x) {
    mma_gemm_body<C3, DIM, true>(g_wq, x, g_tq, DIM * HW, 0);
}
__global__ void __launch_bounds__(256) mma_kv_kernel(const float* __restrict__ x) {
    mma_gemm_body<C1, 2 * DIM, true>(g_wkv, x, g_tkv, DIM * HW, C3 * HW);
}
__global__ void __launch_bounds__(256) mma_o_kernel(float* __restrict__ out) {
    mma_gemm_body<DIM, DIM, false>(g_Wc, g_v, out, DIM * HW, 0);
}

// ---------------------------------------------------------------------------
// Fused: dwconv(q) + dwconv(k) + L2 sum-of-squares + 32x32 Gram per head.
// One image row per chunk; 4 rows per block. SMEM ~40 KB -> 4 blocks/SM.
// ---------------------------------------------------------------------------
#define FP      132
#define QC_OFF  0
#define KC_OFF  (32 * FP)            // 4224
#define SG_OFF  (2 * 32 * FP)        // 8448
#define SN_OFF  (SG_OFF + 1024)      // 9472
#define WS_OFF  (SN_OFF + 64)        // 9536
#define FUSED_SMEM_BYTES ((WS_OFF + 576) * 4)   // 40448

__global__ void __launch_bounds__(256, 4) fused_qk_gram_kernel(
        const float* __restrict__ w_qdw, const float* __restrict__ w_kvdw) {
    extern __shared__ float sf[];
    const int h = blockIdx.y, b = blockIdx.z;
    const int t = threadIdx.x;
    const int w = t >> 5, lane = t & 31;
    const int yb = blockIdx.x * 4;

    const float* qbase = g_tq  + ((size_t)b * DIM     + h * HD) * HW;
    const float* kbase = g_tkv + ((size_t)b * 2 * DIM + h * HD) * HW;

    for (int i = t; i < 1024 + 64; i += 256) sf[SG_OFF + i] = 0.f;
    for (int i = t; i < 2 * HD * 9; i += 256) {
        int tens = i / 288, r = i % 288;
        sf[WS_OFF + i] = (tens ? w_kvdw : w_qdw)[(h * HD) * 9 + r];
    }
    __syncthreads();

    float acc[4][4] = {};
    const int seg = t >> 6, tt = t & 63, i4 = tt >> 3, j4 = tt & 7;

    #pragma unroll 1
    for (int ch = 0; ch < 4; ch++) {
        const int oy = yb + ch;
        // ---- conv: 64 tasks (2 tensors x 32 ch), one row each, 8 per warp
        #pragma unroll 1
        for (int i = 0; i < 8; i++) {
            int task = w + 8 * i;
            int tens = task >> 5;
            int c = task & 31;
            const float* plane = (tens ? kbase : qbase) + (size_t)c * HW;
            float4 r0 = (oy > 0)
                ? *reinterpret_cast<const float4*>(plane + (size_t)(oy - 1) * IMG + lane * 4)
                : make_float4(0.f, 0.f, 0.f, 0.f);
            float4 r1 = *reinterpret_cast<const float4*>(plane + (size_t)oy * IMG + lane * 4);
            float4 r2 = (oy < IMG - 1)
                ? *reinterpret_cast<const float4*>(plane + (size_t)(oy + 1) * IMG + lane * 4)
                : make_float4(0.f, 0.f, 0.f, 0.f);
            float l0 = __shfl_up_sync(0xffffffffu, r0.w, 1);
            float l1 = __shfl_up_sync(0xffffffffu, r1.w, 1);
            float l2 = __shfl_up_sync(0xffffffffu, r2.w, 1);
            float h0 = __shfl_down_sync(0xffffffffu, r0.x, 1);
            float h1 = __shfl_down_sync(0xffffffffu, r1.x, 1);
            float h2 = __shfl_down_sync(0xffffffffu, r2.x, 1);
            if (lane == 0)  { l0 = 0.f; l1 = 0.f; l2 = 0.f; }
            if (lane == 31) { h0 = 0.f; h1 = 0.f; h2 = 0.f; }
            const float* w9 = sf + WS_OFF + tens * 288 + c * 9;
            float wa = w9[0], wb = w9[1], wc = w9[2];
            float wd = w9[3], we = w9[4], wf = w9[5];
            float wg = w9[6], wh = w9[7], wi = w9[8];
            float o0 = wa*l0   + wb*r0.x + wc*r0.y + wd*l1   + we*r1.x + wf*r1.y + wg*l2   + wh*r2.x + wi*r2.y;
            float o1 = wa*r0.x + wb*r0.y + wc*r0.z + wd*r1.x + we*r1.y + wf*r1.z + wg*r2.x + wh*r2.y + wi*r2.z;
            float o2 = wa*r0.y + wb*r0.z + wc*r0.w + wd*r1.y + we*r1.z + wf*r1.w + wg*r2.y + wh*r2.z + wi*r2.w;
            float o3 = wa*r0.z + wb*r0.w + wc*h0   + wd*r1.z + we*r1.w + wf*h1   + wg*r2.z + wh*r2.w + wi*h2;
            *reinterpret_cast<float4*>(sf + (tens ? KC_OFF : QC_OFF) + c * FP + lane * 4) =
                make_float4(o0, o1, o2, o3);
            float ssq = o0*o0 + o1*o1 + o2*o2 + o3*o3;
            #pragma unroll
            for (int off = 16; off > 0; off >>= 1)
                ssq += __shfl_down_sync(0xffffffffu, ssq, off);
            if (lane == 0) atomicAdd(&sf[SN_OFF + tens * HD + c], ssq);
        }
        __syncthreads();
        // ---- gram over this row (128 px), each seg handles 32 px
        const float* QCp = sf + QC_OFF;
        const float* KCp = sf + KC_OFF;
        #pragma unroll 2
        for (int jj = seg * 32; jj < seg * 32 + 32; jj += 4) {
            float4 q4[4], k4[4];
            #pragma unroll
            for (int r = 0; r < 4; r++)
                q4[r] = *reinterpret_cast<const float4*>(&QCp[(i4 + 8 * r) * FP + jj]);
            #pragma unroll
            for (int s = 0; s < 4; s++)
                k4[s] = *reinterpret_cast<const float4*>(&KCp[(j4 + 8 * s) * FP + jj]);
            #pragma unroll
            for (int r = 0; r < 4; r++)
                #pragma unroll
                for (int s = 0; s < 4; s++)
                    acc[r][s] += q4[r].x * k4[s].x + q4[r].y * k4[s].y
                               + q4[r].z * k4[s].z + q4[r].w * k4[s].w;
        }
        __syncthreads();
    }
    #pragma unroll
    for (int r = 0; r < 4; r++)
        #pragma unroll
        for (int s = 0; s < 4; s++)
            atomicAdd(&sf[SG_OFF + (i4 + 8 * r) * HD + (j4 + 8 * s)], acc[r][s]);
    __syncthreads();
    float* Gp = g_G + (size_t)(b * HEADS + h) * HD * HD;
    for (int e = t; e < HD * HD; e += 256) atomicAdd(&Gp[e], sf[SG_OFF + e]);
    if (t < 64) {
        float* np = (t < HD) ? g_nq : g_nk;
        atomicAdd(&np[b * DIM + h * HD + (t & 31)], sf[SN_OFF + t]);
    }
}

// ---------------------------------------------------------------------------
// Depthwise 3x3 conv for V (stores tf32 bits for the o-GEMM)
// ---------------------------------------------------------------------------
__global__ void __launch_bounds__(256) dwv_kernel(const float* __restrict__ w9) {
    int b = blockIdx.z, c = blockIdx.y, chunk = blockIdx.x;
    const float* ip = g_tkv + ((size_t)b * 2 * DIM + DIM + c) * HW;
    float*       op = g_v   + ((size_t)b * DIM + c) * HW;
    float wv[9];
    #pragma unroll
    for (int i = 0; i < 9; i++) wv[i] = w9[(DIM + c) * 9 + i];
    #pragma unroll
    for (int it = 0; it < 8; it++) {
        int p = chunk * 2048 + it * 256 + threadIdx.x;
        int y = p >> 7, x = p & 127;
        float s = 0.f;
        #pragma unroll
        for (int dy = -1; dy <= 1; dy++) {
            int yy = y + dy;
            if ((unsigned)yy < (unsigned)IMG) {
                const float* rp = ip + yy * IMG;
                #pragma unroll
                for (int dx = -1; dx <= 1; dx++) {
                    int xx = x + dx;
                    if ((unsigned)xx < (unsigned)IMG)
                        s += wv[(dy + 1) * 3 + dx + 1] * rp[xx];
                }
            }
        }
        op[p] = f2tff(s);
    }
}

// ---------------------------------------------------------------------------
// Softmax + fold attention into w_proj (stores tf32 bits)
// ---------------------------------------------------------------------------
__global__ void __launch_bounds__(256) attn_wc_kernel(const float* __restrict__ temp,
                                                      const float* __restrict__ w_proj) {
    int h = blockIdx.x, b = blockIdx.y;
    int t = threadIdx.x;
    __shared__ float As[HD][HD + 1];
    __shared__ float qn[HD], kn[HD];

    if (t < HD) {
        qn[t] = fmaxf(sqrtf(g_nq[b * DIM + h * HD + t]), 1e-12f);
        kn[t] = fmaxf(sqrtf(g_nk[b * DIM + h * HD + t]), 1e-12f);
    }
    __syncthreads();
    if (t < HD) {
        int c = t;
        float T = temp[h];
        float inq = T / qn[c];
        const float* Gp = &g_G[((size_t)(b * HEADS + h) * HD + c) * HD];
        float rowv[HD];
        float m = -1e30f;
        #pragma unroll
        for (int d = 0; d < HD; d++) {
            float v = Gp[d] * inq / kn[d];
            rowv[d] = v;
            m = fmaxf(m, v);
        }
        float ssum = 0.f;
        #pragma unroll
        for (int d = 0; d < HD; d++) { rowv[d] = expf(rowv[d] - m); ssum += rowv[d]; }
        float inv = 1.f / ssum;
        #pragma unroll
        for (int d = 0; d < HD; d++) As[c][d] = rowv[d] * inv;
    }
    __syncthreads();

    int o = t;
    float wp[HD];
    #pragma unroll
    for (int c = 0; c < HD; c++) wp[c] = w_proj[o * DIM + h * HD + c];
    #pragma unroll 4
    for (int d = 0; d < HD; d++) {
        float s = 0.f;
        #pragma unroll
        for (int c = 0; c < HD; c++) s += wp[c] * As[c][d];
        g_Wc[((size_t)b * DIM + o) * DIM + h * HD + d] = f2tff(s);
    }
}

// ---------------------------------------------------------------------------
// Launch
// ---------------------------------------------------------------------------
extern "C" void kernel_launch(void* const* d_in, const int* in_sizes, int n_in,
                              void* d_out, int out_size) {
    const float* x      = (const float*)d_in[0];
    const float* k_v    = (const float*)d_in[1];
    const float* temper = (const float*)d_in[2];
    const float* w_kR   = (const float*)d_in[3];
    const float* w_kI   = (const float*)d_in[4];
    const float* w_qR   = (const float*)d_in[5];
    const float* w_qdw  = (const float*)d_in[6];
    const float* w_kvI  = (const float*)d_in[7];
    const float* w_kvdw = (const float*)d_in[8];
    const float* w_proj = (const float*)d_in[9];
    float* out = (float*)d_out;

    cudaFuncSetAttribute(mma_q_kernel,  cudaFuncAttributeMaxDynamicSharedMemorySize, SMEM_TOTAL);
    cudaFuncSetAttribute(mma_kv_kernel, cudaFuncAttributeMaxDynamicSharedMemorySize, SMEM_TOTAL);
    cudaFuncSetAttribute(mma_o_kernel,  cudaFuncAttributeMaxDynamicSharedMemorySize, SMEM_TOTAL);
    cudaFuncSetAttribute(fused_qk_gram_kernel, cudaFuncAttributeMaxDynamicSharedMemorySize, FUSED_SMEM_BYTES);

    modk_kernel<<<BATCH, 256>>>(k_v, w_kR, w_kI, w_qR, w_kvI);
    mma_q_kernel <<<dim3(HW / 128, DIM / 128,     BATCH), 256, SMEM_TOTAL>>>(x);
    mma_kv_kernel<<<dim3(HW / 128, 2 * DIM / 128, BATCH), 256, SMEM_TOTAL>>>(x);
    fused_qk_gram_kernel<<<dim3(32, HEADS, BATCH), 256, FUSED_SMEM_BYTES>>>(w_qdw, w_kvdw);
    dwv_kernel<<<dim3(8, DIM, BATCH), 256>>>(w_kvdw);
    attn_wc_kernel<<<dim3(HEADS, BATCH), 256>>>(temper, w_proj);
    mma_o_kernel<<<dim3(HW / 128, DIM / 128, BATCH), 256, SMEM_TOTAL>>>(out);
}

// round 12
// speedup vs baseline: 1.3917x; 1.0161x over previous
#include <cuda_runtime.h>
#include <cuda_bf16.h>
#include <math.h>
#include <stdint.h>

// Problem constants
#define BATCH 4
#define DIM   256
#define C3    192
#define C1    64
#define HEADS 8
#define HD    32
#define HW    16384   // 128*128
#define IMG   128

// ---------------------------------------------------------------------------
// Device scratch
// ---------------------------------------------------------------------------
__device__ float g_wq [BATCH * DIM * C3];        // tf32 bits
__device__ float g_wkv[BATCH * 2*DIM * C1];      // tf32 bits
__device__ float g_tq [BATCH * DIM * HW];        // q pre-dwconv (fp32)
__device__ float g_tkv[BATCH * 2*DIM * HW];      // kv pre-dwconv (fp32)
__device__ float g_v  [BATCH * DIM * HW];        // v post-dwconv (tf32 bits)
__device__ float g_nq [BATCH * DIM];
__device__ float g_nk [BATCH * DIM];
__device__ float g_G  [BATCH * HEADS * HD * HD];
__device__ float g_Wc [BATCH * DIM * DIM];       // tf32 bits

// ---------------------------------------------------------------------------
// Helpers
// ---------------------------------------------------------------------------
__device__ __forceinline__ uint32_t smem_u32(const void* p) {
    uint32_t a;
    asm("{ .reg .u64 t; cvta.to.shared.u64 t, %1; cvt.u32.u64 %0, t; }" : "=r"(a) : "l"(p));
    return a;
}
__device__ __forceinline__ uint32_t f2tf(float x) {
    uint32_t r; asm("cvt.rna.tf32.f32 %0, %1;" : "=r"(r) : "f"(x)); return r;
}
__device__ __forceinline__ float f2tff(float x) {
    return __uint_as_float(f2tf(x));
}
#define CPA16(dst, src) asm volatile("cp.async.cg.shared.global [%0], [%1], 16;" :: "r"(dst), "l"(src) : "memory")
#define CPA_COMMIT()    asm volatile("cp.async.commit_group;" ::: "memory")
#define CPA_WAIT(n)     asm volatile("cp.async.wait_group %0;" :: "n"(n) : "memory")

__device__ __forceinline__ void mma_tf32(float* c, const uint32_t* a, const uint32_t* b) {
    asm volatile(
        "mma.sync.aligned.m16n8k8.row.col.f32.tf32.tf32.f32 "
        "{%0,%1,%2,%3}, {%4,%5,%6,%7}, {%8,%9}, {%0,%1,%2,%3};"
        : "+f"(c[0]), "+f"(c[1]), "+f"(c[2]), "+f"(c[3])
        : "r"(a[0]), "r"(a[1]), "r"(a[2]), "r"(a[3]), "r"(b[0]), "r"(b[1]));
}

// GEMM SMEM layout constants (bytes)
#define A_PITCH  36
#define B_PITCH  136
#define A_BYTES  (128 * A_PITCH * 4)          // 18432
#define B_BYTES  (32 * B_PITCH * 4)           // 17408
#define STAGE_BYTES (A_BYTES + B_BYTES)       // 35840
#define SMEM_TOTAL (3 * STAGE_BYTES)          // 107520 (3-stage)
#define C_PITCH  68

// ---------------------------------------------------------------------------
// FiLM folded into per-batch weights (pre-converted to tf32 bits) + zeroing
// ---------------------------------------------------------------------------
__global__ void modk_kernel(const float* __restrict__ k_v,
                            const float* __restrict__ w_kR,
                            const float* __restrict__ w_kI,
                            const float* __restrict__ w_qR,
                            const float* __restrict__ w_kvI) {
    int b = blockIdx.x;
    int t = threadIdx.x;
    __shared__ float sc[DIM];
    if (t < C3) {
        float s = 0.f;
        const float* kb = k_v + b * 256;
        for (int i = 0; i < 192; i++) s += kb[i] * w_kR[t * 192 + i];
        sc[t] = 1.f + s;
    } else {
        int o = t - C3;
        float s = 0.f;
        const float* kb = k_v + b * 256 + 192;
        for (int i = 0; i < 64; i++) s += kb[i] * w_kI[o * 64 + i];
        sc[t] = 1.f + s;
    }
    __syncthreads();
    for (int idx = t; idx < DIM * C3; idx += blockDim.x)
        g_wq[b * DIM * C3 + idx] = f2tff(w_qR[idx] * sc[idx % C3]);
    for (int idx = t; idx < 2 * DIM * C1; idx += blockDim.x)
        g_wkv[b * 2 * DIM * C1 + idx] = f2tff(w_kvI[idx] * sc[C3 + (idx & 63)]);
    for (int i = t; i < DIM; i += blockDim.x) {
        g_nq[b * DIM + i] = 0.f;
        g_nk[b * DIM + i] = 0.f;
    }
    for (int i = t; i < HEADS * HD * HD; i += blockDim.x)
        g_G[b * HEADS * HD * HD + i] = 0.f;
}

// ---------------------------------------------------------------------------
// tf32 mma.sync GEMM, 3-stage cp.async pipeline.
// A (weights) is pre-converted tf32 bits. B is raw fp32 when CVT_FRAG
// (converted at fragment load), or pre-converted (o-GEMM).
// ---------------------------------------------------------------------------
template <int K, int OC, bool CVT_FRAG>
__device__ __forceinline__ void mma_gemm_body(const float* __restrict__ W,
                                              const float* __restrict__ X,
                                              float* __restrict__ C,
                                              int x_bstride, int x_off) {
    extern __shared__ char smem[];
    const int b  = blockIdx.z;
    const int n0 = blockIdx.x * 128;
    const int o0 = blockIdx.y * 128;
    const float* Wb = W + (size_t)b * OC * K + (size_t)o0 * K;
    const float* Xb = X + (size_t)b * x_bstride + x_off + n0;
    float*       Cb = C + (size_t)b * OC * HW + (size_t)o0 * HW + n0;

    const int t = threadIdx.x;
    const int warp = t >> 5, lane = t & 31;
    const int wm = warp >> 2, wn = warp & 3;
    const int g = lane >> 2, tg = lane & 3;

    const uint32_t sbase = smem_u32(smem);
    const int am = t >> 3;
    const int a16 = (t & 7) * 16;
    const int bn16 = (t & 31) * 16;
    const int bk = t >> 5;

    float acc[4][4][4];
    #pragma unroll
    for (int i = 0; i < 4; i++)
        #pragma unroll
        for (int j = 0; j < 4; j++)
            #pragma unroll
            for (int r = 0; r < 4; r++) acc[i][j][r] = 0.f;

    constexpr int NCHUNK = K / 32;

    // issue chunk `c` into stage buffer at byte offset `soff`
    auto issue_chunk = [&](int c, uint32_t soff) {
        const int k0 = c * 32;
        uint32_t ab = sbase + soff;
        uint32_t bb = ab + A_BYTES;
        #pragma unroll
        for (int i = 0; i < 4; i++) {
            int m = am + 32 * i;
            CPA16(ab + m * (A_PITCH * 4) + a16, Wb + (size_t)m * K + k0 + (a16 >> 2));
        }
        #pragma unroll
        for (int i = 0; i < 4; i++) {
            int kk = bk + 8 * i;
            CPA16(bb + kk * (B_PITCH * 4) + bn16, Xb + (size_t)(k0 + kk) * HW + (bn16 >> 2));
        }
    };

    // prologue: chunks 0 and 1 in flight (NCHUNK >= 2 always)
    issue_chunk(0, 0);
    CPA_COMMIT();
    issue_chunk(1, STAGE_BYTES);
    CPA_COMMIT();

    int sc_issue = 2 * STAGE_BYTES;   // stage offset for chunk c+2
    int sc_comp  = 0;                 // stage offset for chunk c

    #pragma unroll 1
    for (int c = 0; c < NCHUNK; c++) {
        if (c + 2 < NCHUNK) issue_chunk(c + 2, sc_issue);
        CPA_COMMIT();
        CPA_WAIT(2);
        __syncthreads();

        const uint32_t* Asu = reinterpret_cast<const uint32_t*>(smem + sc_comp);
        const uint32_t* Bsu = reinterpret_cast<const uint32_t*>(smem + sc_comp + A_BYTES);
        const float*    Bsf = reinterpret_cast<const float*>(smem + sc_comp + A_BYTES);

        #pragma unroll
        for (int ks = 0; ks < 4; ks++) {
            uint32_t afr[4][4];
            #pragma unroll
            for (int mf = 0; mf < 4; mf++) {
                int m = wm * 64 + mf * 16 + g;
                int k = ks * 8 + tg;
                afr[mf][0] = Asu[m * A_PITCH + k];
                afr[mf][1] = Asu[(m + 8) * A_PITCH + k];
                afr[mf][2] = Asu[m * A_PITCH + k + 4];
                afr[mf][3] = Asu[(m + 8) * A_PITCH + k + 4];
            }
            uint32_t bfr[4][2];
            #pragma unroll
            for (int nf = 0; nf < 4; nf++) {
                int n = wn * 32 + nf * 8 + g;
                int k = ks * 8 + tg;
                if (CVT_FRAG) {
                    bfr[nf][0] = f2tf(Bsf[k * B_PITCH + n]);
                    bfr[nf][1] = f2tf(Bsf[(k + 4) * B_PITCH + n]);
                } else {
                    bfr[nf][0] = Bsu[k * B_PITCH + n];
                    bfr[nf][1] = Bsu[(k + 4) * B_PITCH + n];
                }
            }
            #pragma unroll
            for (int mf = 0; mf < 4; mf++)
                #pragma unroll
                for (int nf = 0; nf < 4; nf++)
                    mma_tf32(acc[mf][nf], afr[mf], bfr[nf]);
        }
        __syncthreads();

        // advance stage ring
        sc_issue += STAGE_BYTES; if (sc_issue == 3 * STAGE_BYTES) sc_issue = 0;
        sc_comp  += STAGE_BYTES; if (sc_comp  == 3 * STAGE_BYTES) sc_comp  = 0;
    }

    // epilogue: stage through SMEM, coalesced 16B stores
    float* Cs = reinterpret_cast<float*>(smem);
    #pragma unroll
    for (int half = 0; half < 2; half++) {
        if ((wn >> 1) == half) {
            int cb = wn * 32 - half * 64;
            #pragma unroll
            for (int mf = 0; mf < 4; mf++) {
                #pragma unroll
                for (int nf = 0; nf < 4; nf++) {
                    int row = wm * 64 + mf * 16 + g;
                    int col = cb + nf * 8 + tg * 2;
                    *reinterpret_cast<float2*>(&Cs[row * C_PITCH + col]) =
                        make_float2(acc[mf][nf][0], acc[mf][nf][1]);
                    *reinterpret_cast<float2*>(&Cs[(row + 8) * C_PITCH + col]) =
                        make_float2(acc[mf][nf][2], acc[mf][nf][3]);
                }
            }
        }
        __syncthreads();
        #pragma unroll
        for (int i = 0; i < 8; i++) {
            int r = (t >> 4) + 16 * i;
            int col = (t & 15) * 4;
            float4 v = *reinterpret_cast<const float4*>(&Cs[r * C_PITCH + col]);
            *reinterpret_cast<float4*>(&Cb[(size_t)r * HW + half * 64 + col]) = v;
        }
        __syncthreads();
    }
}

__global__ void __launch_bounds__(256) mma_q_kernel(const float* __restrict__ x) {
    mma_gemm_body<C3, DIM, true>(g_wq, x, g_tq, DIM * HW, 0);
}
__global__ void __launch_bounds__(256) mma_kv_kernel(const float* __restrict__ x) {
    mma_gemm_body<C1, 2 * DIM, true>(g_wkv, x, g_tkv, DIM * HW, C3 * HW);
}
__global__ void __launch_bounds__(256) mma_o_kernel(float* __restrict__ out) {
    mma_gemm_body<DIM, DIM, false>(g_Wc, g_v, out, DIM * HW, 0);
}

// ---------------------------------------------------------------------------
// Fused: dwconv(q) + dwconv(k) + L2 sum-of-squares + 32x32 Gram per head.
// One image row per chunk; 4 rows per block. SMEM ~40 KB -> 4 blocks/SM.
// ---------------------------------------------------------------------------
#define FP      132
#define QC_OFF  0
#define KC_OFF  (32 * FP)            // 4224
#define SG_OFF  (2 * 32 * FP)        // 8448
#define SN_OFF  (SG_OFF + 1024)      // 9472
#define WS_OFF  (SN_OFF + 64)        // 9536
#define FUSED_SMEM_BYTES ((WS_OFF + 576) * 4)   // 40448

__global__ void __launch_bounds__(256, 4) fused_qk_gram_kernel(
        const float* __restrict__ w_qdw, const float* __restrict__ w_kvdw) {
    extern __shared__ float sf[];
    const int h = blockIdx.y, b = blockIdx.z;
    const int t = threadIdx.x;
    const int w = t >> 5, lane = t & 31;
    const int yb = blockIdx.x * 4;

    const float* qbase = g_tq  + ((size_t)b * DIM     + h * HD) * HW;
    const float* kbase = g_tkv + ((size_t)b * 2 * DIM + h * HD) * HW;

    for (int i = t; i < 1024 + 64; i += 256) sf[SG_OFF + i] = 0.f;
    for (int i = t; i < 2 * HD * 9; i += 256) {
        int tens = i / 288, r = i % 288;
        sf[WS_OFF + i] = (tens ? w_kvdw : w_qdw)[(h * HD) * 9 + r];
    }
    __syncthreads();

    float acc[4][4] = {};
    const int seg = t >> 6, tt = t & 63, i4 = tt >> 3, j4 = tt & 7;

    #pragma unroll 1
    for (int ch = 0; ch < 4; ch++) {
        const int oy = yb + ch;
        #pragma unroll 1
        for (int i = 0; i < 8; i++) {
            int task = w + 8 * i;
            int tens = task >> 5;
            int c = task & 31;
            const float* plane = (tens ? kbase : qbase) + (size_t)c * HW;
            float4 r0 = (oy > 0)
                ? *reinterpret_cast<const float4*>(plane + (size_t)(oy - 1) * IMG + lane * 4)
                : make_float4(0.f, 0.f, 0.f, 0.f);
            float4 r1 = *reinterpret_cast<const float4*>(plane + (size_t)oy * IMG + lane * 4);
            float4 r2 = (oy < IMG - 1)
                ? *reinterpret_cast<const float4*>(plane + (size_t)(oy + 1) * IMG + lane * 4)
                : make_float4(0.f, 0.f, 0.f, 0.f);
            float l0 = __shfl_up_sync(0xffffffffu, r0.w, 1);
            float l1 = __shfl_up_sync(0xffffffffu, r1.w, 1);
            float l2 = __shfl_up_sync(0xffffffffu, r2.w, 1);
            float h0 = __shfl_down_sync(0xffffffffu, r0.x, 1);
            float h1 = __shfl_down_sync(0xffffffffu, r1.x, 1);
            float h2 = __shfl_down_sync(0xffffffffu, r2.x, 1);
            if (lane == 0)  { l0 = 0.f; l1 = 0.f; l2 = 0.f; }
            if (lane == 31) { h0 = 0.f; h1 = 0.f; h2 = 0.f; }
            const float* w9 = sf + WS_OFF + tens * 288 + c * 9;
            float wa = w9[0], wb = w9[1], wc = w9[2];
            float wd = w9[3], we = w9[4], wf = w9[5];
            float wg = w9[6], wh = w9[7], wi = w9[8];
            float o0 = wa*l0   + wb*r0.x + wc*r0.y + wd*l1   + we*r1.x + wf*r1.y + wg*l2   + wh*r2.x + wi*r2.y;
            float o1 = wa*r0.x + wb*r0.y + wc*r0.z + wd*r1.x + we*r1.y + wf*r1.z + wg*r2.x + wh*r2.y + wi*r2.z;
            float o2 = wa*r0.y + wb*r0.z + wc*r0.w + wd*r1.y + we*r1.z + wf*r1.w + wg*r2.y + wh*r2.z + wi*r2.w;
            float o3 = wa*r0.z + wb*r0.w + wc*h0   + wd*r1.z + we*r1.w + wf*h1   + wg*r2.z + wh*r2.w + wi*h2;
            *reinterpret_cast<float4*>(sf + (tens ? KC_OFF : QC_OFF) + c * FP + lane * 4) =
                make_float4(o0, o1, o2, o3);
            float ssq = o0*o0 + o1*o1 + o2*o2 + o3*o3;
            #pragma unroll
            for (int off = 16; off > 0; off >>= 1)
                ssq += __shfl_down_sync(0xffffffffu, ssq, off);
            if (lane == 0) atomicAdd(&sf[SN_OFF + tens * HD + c], ssq);
        }
        __syncthreads();
        const float* QCp = sf + QC_OFF;
        const float* KCp = sf + KC_OFF;
        #pragma unroll 2
        for (int jj = seg * 32; jj < seg * 32 + 32; jj += 4) {
            float4 q4[4], k4[4];
            #pragma unroll
            for (int r = 0; r < 4; r++)
                q4[r] = *reinterpret_cast<const float4*>(&QCp[(i4 + 8 * r) * FP + jj]);
            #pragma unroll
            for (int s = 0; s < 4; s++)
                k4[s] = *reinterpret_cast<const float4*>(&KCp[(j4 + 8 * s) * FP + jj]);
            #pragma unroll
            for (int r = 0; r < 4; r++)
                #pragma unroll
                for (int s = 0; s < 4; s++)
                    acc[r][s] += q4[r].x * k4[s].x + q4[r].y * k4[s].y
                               + q4[r].z * k4[s].z + q4[r].w * k4[s].w;
        }
        __syncthreads();
    }
    #pragma unroll
    for (int r = 0; r < 4; r++)
        #pragma unroll
        for (int s = 0; s < 4; s++)
            atomicAdd(&sf[SG_OFF + (i4 + 8 * r) * HD + (j4 + 8 * s)], acc[r][s]);
    __syncthreads();
    float* Gp = g_G + (size_t)(b * HEADS + h) * HD * HD;
    for (int e = t; e < HD * HD; e += 256) atomicAdd(&Gp[e], sf[SG_OFF + e]);
    if (t < 64) {
        float* np = (t < HD) ? g_nq : g_nk;
        atomicAdd(&np[b * DIM + h * HD + (t & 31)], sf[SN_OFF + t]);
    }
}

// ---------------------------------------------------------------------------
// Depthwise 3x3 conv for V (stores tf32 bits for the o-GEMM)
// ---------------------------------------------------------------------------
__global__ void __launch_bounds__(256) dwv_kernel(const float* __restrict__ w9) {
    int b = blockIdx.z, c = blockIdx.y, chunk = blockIdx.x;
    const float* ip = g_tkv + ((size_t)b * 2 * DIM + DIM + c) * HW;
    float*       op = g_v   + ((size_t)b * DIM + c) * HW;
    float wv[9];
    #pragma unroll
    for (int i = 0; i < 9; i++) wv[i] = w9[(DIM + c) * 9 + i];
    #pragma unroll
    for (int it = 0; it < 8; it++) {
        int p = chunk * 2048 + it * 256 + threadIdx.x;
        int y = p >> 7, x = p & 127;
        float s = 0.f;
        #pragma unroll
        for (int dy = -1; dy <= 1; dy++) {
            int yy = y + dy;
            if ((unsigned)yy < (unsigned)IMG) {
                const float* rp = ip + yy * IMG;
                #pragma unroll
                for (int dx = -1; dx <= 1; dx++) {
                    int xx = x + dx;
                    if ((unsigned)xx < (unsigned)IMG)
                        s += wv[(dy + 1) * 3 + dx + 1] * rp[xx];
                }
            }
        }
        op[p] = f2tff(s);
    }
}

// ---------------------------------------------------------------------------
// Softmax + fold attention into w_proj (stores tf32 bits)
// ---------------------------------------------------------------------------
__global__ void __launch_bounds__(256) attn_wc_kernel(const float* __restrict__ temp,
                                                      const float* __restrict__ w_proj) {
    int h = blockIdx.x, b = blockIdx.y;
    int t = threadIdx.x;
    __shared__ float As[HD][HD + 1];
    __shared__ float qn[HD], kn[HD];

    if (t < HD) {
        qn[t] = fmaxf(sqrtf(g_nq[b * DIM + h * HD + t]), 1e-12f);
        kn[t] = fmaxf(sqrtf(g_nk[b * DIM + h * HD + t]), 1e-12f);
    }
    __syncthreads();
    if (t < HD) {
        int c = t;
        float T = temp[h];
        float inq = T / qn[c];
        const float* Gp = &g_G[((size_t)(b * HEADS + h) * HD + c) * HD];
        float rowv[HD];
        float m = -1e30f;
        #pragma unroll
        for (int d = 0; d < HD; d++) {
            float v = Gp[d] * inq / kn[d];
            rowv[d] = v;
            m = fmaxf(m, v);
        }
        float ssum = 0.f;
        #pragma unroll
        for (int d = 0; d < HD; d++) { rowv[d] = expf(rowv[d] - m); ssum += rowv[d]; }
        float inv = 1.f / ssum;
        #pragma unroll
        for (int d = 0; d < HD; d++) As[c][d] = rowv[d] * inv;
    }
    __syncthreads();

    int o = t;
    float wp[HD];
    #pragma unroll
    for (int c = 0; c < HD; c++) wp[c] = w_proj[o * DIM + h * HD + c];
    #pragma unroll 4
    for (int d = 0; d < HD; d++) {
        float s = 0.f;
        #pragma unroll
        for (int c = 0; c < HD; c++) s += wp[c] * As[c][d];
        g_Wc[((size_t)b * DIM + o) * DIM + h * HD + d] = f2tff(s);
    }
}

// ---------------------------------------------------------------------------
// Launch
// ---------------------------------------------------------------------------
extern "C" void kernel_launch(void* const* d_in, const int* in_sizes, int n_in,
                              void* d_out, int out_size) {
    const float* x      = (const float*)d_in[0];
    const float* k_v    = (const float*)d_in[1];
    const float* temper = (const float*)d_in[2];
    const float* w_kR   = (const float*)d_in[3];
    const float* w_kI   = (const float*)d_in[4];
    const float* w_qR   = (const float*)d_in[5];
    const float* w_qdw  = (const float*)d_in[6];
    const float* w_kvI  = (const float*)d_in[7];
    const float* w_kvdw = (const float*)d_in[8];
    const float* w_proj = (const float*)d_in[9];
    float* out = (float*)d_out;

    cudaFuncSetAttribute(mma_q_kernel,  cudaFuncAttributeMaxDynamicSharedMemorySize, SMEM_TOTAL);
    cudaFuncSetAttribute(mma_kv_kernel, cudaFuncAttributeMaxDynamicSharedMemorySize, SMEM_TOTAL);
    cudaFuncSetAttribute(mma_o_kernel,  cudaFuncAttributeMaxDynamicSharedMemorySize, SMEM_TOTAL);
    cudaFuncSetAttribute(fused_qk_gram_kernel, cudaFuncAttributeMaxDynamicSharedMemorySize, FUSED_SMEM_BYTES);

    modk_kernel<<<BATCH, 256>>>(k_v, w_kR, w_kI, w_qR, w_kvI);
    mma_q_kernel <<<dim3(HW / 128, DIM / 128,     BATCH), 256, SMEM_TOTAL>>>(x);
    mma_kv_kernel<<<dim3(HW / 128, 2 * DIM / 128, BATCH), 256, SMEM_TOTAL>>>(x);
    fused_qk_gram_kernel<<<dim3(32, HEADS, BATCH), 256, FUSED_SMEM_BYTES>>>(w_qdw, w_kvdw);
    dwv_kernel<<<dim3(8, DIM, BATCH), 256>>>(w_kvdw);
    attn_wc_kernel<<<dim3(HEADS, BATCH), 256>>>(temper, w_proj);
    mma_o_kernel<<<dim3(HW / 128, DIM / 128, BATCH), 256, SMEM_TOTAL>>>(out);
}

// round 14
// speedup vs baseline: 1.3987x; 1.0050x over previous
#include <cuda_runtime.h>
#include <cuda_bf16.h>
#include <math.h>
#include <stdint.h>

// Problem constants
#define BATCH 4
#define DIM   256
#define C3    192
#define C1    64
#define HEADS 8
#define HD    32
#define HW    16384   // 128*128
#define IMG   128

// ---------------------------------------------------------------------------
// Device scratch
// ---------------------------------------------------------------------------
__device__ float g_wq [BATCH * DIM * C3];        // tf32 bits
__device__ float g_wkv[BATCH * 2*DIM * C1];      // tf32 bits
__device__ float g_tq [BATCH * DIM * HW];        // q pre-dwconv (fp32)
__device__ float g_tkv[BATCH * 2*DIM * HW];      // kv pre-dwconv (fp32)
__device__ float g_v  [BATCH * DIM * HW];        // v post-dwconv (tf32 bits)
__device__ float g_nq [BATCH * DIM];
__device__ float g_nk [BATCH * DIM];
__device__ float g_G  [BATCH * HEADS * HD * HD];
__device__ float g_Wc [BATCH * DIM * DIM];       // tf32 bits

// ---------------------------------------------------------------------------
// Helpers
// ---------------------------------------------------------------------------
__device__ __forceinline__ uint32_t smem_u32(const void* p) {
    uint32_t a;
    asm("{ .reg .u64 t; cvta.to.shared.u64 t, %1; cvt.u32.u64 %0, t; }" : "=r"(a) : "l"(p));
    return a;
}
__device__ __forceinline__ uint32_t f2tf(float x) {
    uint32_t r; asm("cvt.rna.tf32.f32 %0, %1;" : "=r"(r) : "f"(x)); return r;
}
__device__ __forceinline__ float f2tff(float x) {
    return __uint_as_float(f2tf(x));
}
#define CPA16(dst, src) asm volatile("cp.async.cg.shared.global [%0], [%1], 16;" :: "r"(dst), "l"(src) : "memory")
#define CPA_COMMIT()    asm volatile("cp.async.commit_group;" ::: "memory")
#define CPA_WAIT(n)     asm volatile("cp.async.wait_group %0;" :: "n"(n) : "memory")

__device__ __forceinline__ void mma_tf32(float* c, const uint32_t* a, const uint32_t* b) {
    asm volatile(
        "mma.sync.aligned.m16n8k8.row.col.f32.tf32.tf32.f32 "
        "{%0,%1,%2,%3}, {%4,%5,%6,%7}, {%8,%9}, {%0,%1,%2,%3};"
        : "+f"(c[0]), "+f"(c[1]), "+f"(c[2]), "+f"(c[3])
        : "r"(a[0]), "r"(a[1]), "r"(a[2]), "r"(a[3]), "r"(b[0]), "r"(b[1]));
}

// GEMM SMEM layout constants (bytes)
#define A_PITCH  36
#define B_PITCH  136
#define A_BYTES  (128 * A_PITCH * 4)          // 18432
#define B_BYTES  (32 * B_PITCH * 4)           // 17408
#define STAGE_BYTES (A_BYTES + B_BYTES)       // 35840
#define SMEM_TOTAL (3 * STAGE_BYTES)          // 107520 (3-stage)
#define C_PITCH  68

// ---------------------------------------------------------------------------
// FiLM folded into per-batch weights (pre-converted to tf32 bits) + zeroing
// ---------------------------------------------------------------------------
__global__ void modk_kernel(const float* __restrict__ k_v,
                            const float* __restrict__ w_kR,
                            const float* __restrict__ w_kI,
                            const float* __restrict__ w_qR,
                            const float* __restrict__ w_kvI) {
    int b = blockIdx.x;
    int t = threadIdx.x;
    __shared__ float sc[DIM];
    if (t < C3) {
        float s = 0.f;
        const float* kb = k_v + b * 256;
        for (int i = 0; i < 192; i++) s += kb[i] * w_kR[t * 192 + i];
        sc[t] = 1.f + s;
    } else {
        int o = t - C3;
        float s = 0.f;
        const float* kb = k_v + b * 256 + 192;
        for (int i = 0; i < 64; i++) s += kb[i] * w_kI[o * 64 + i];
        sc[t] = 1.f + s;
    }
    __syncthreads();
    for (int idx = t; idx < DIM * C3; idx += blockDim.x)
        g_wq[b * DIM * C3 + idx] = f2tff(w_qR[idx] * sc[idx % C3]);
    for (int idx = t; idx < 2 * DIM * C1; idx += blockDim.x)
        g_wkv[b * 2 * DIM * C1 + idx] = f2tff(w_kvI[idx] * sc[C3 + (idx & 63)]);
    for (int i = t; i < DIM; i += blockDim.x) {
        g_nq[b * DIM + i] = 0.f;
        g_nk[b * DIM + i] = 0.f;
    }
    for (int i = t; i < HEADS * HD * HD; i += blockDim.x)
        g_G[b * HEADS * HD * HD + i] = 0.f;
}

// ---------------------------------------------------------------------------
// tf32 mma.sync GEMM, 3-stage cp.async pipeline + register double-buffered
// fragments (ks+1 frags load while ks MMAs execute).
// ---------------------------------------------------------------------------
template <int K, int OC, bool CVT_FRAG>
__device__ __forceinline__ void mma_gemm_body(const float* __restrict__ W,
                                              const float* __restrict__ X,
                                              float* __restrict__ C,
                                              int x_bstride, int x_off) {
    extern __shared__ char smem[];
    const int b  = blockIdx.z;
    const int n0 = blockIdx.x * 128;
    const int o0 = blockIdx.y * 128;
    const float* Wb = W + (size_t)b * OC * K + (size_t)o0 * K;
    const float* Xb = X + (size_t)b * x_bstride + x_off + n0;
    float*       Cb = C + (size_t)b * OC * HW + (size_t)o0 * HW + n0;

    const int t = threadIdx.x;
    const int warp = t >> 5, lane = t & 31;
    const int wm = warp >> 2, wn = warp & 3;
    const int g = lane >> 2, tg = lane & 3;

    const uint32_t sbase = smem_u32(smem);
    const int am = t >> 3;
    const int a16 = (t & 7) * 16;
    const int bn16 = (t & 31) * 16;
    const int bk = t >> 5;

    float acc[4][4][4];
    #pragma unroll
    for (int i = 0; i < 4; i++)
        #pragma unroll
        for (int j = 0; j < 4; j++)
            #pragma unroll
            for (int r = 0; r < 4; r++) acc[i][j][r] = 0.f;

    constexpr int NCHUNK = K / 32;

    auto issue_chunk = [&](int c, uint32_t soff) {
        const int k0 = c * 32;
        uint32_t ab = sbase + soff;
        uint32_t bb = ab + A_BYTES;
        #pragma unroll
        for (int i = 0; i < 4; i++) {
            int m = am + 32 * i;
            CPA16(ab + m * (A_PITCH * 4) + a16, Wb + (size_t)m * K + k0 + (a16 >> 2));
        }
        #pragma unroll
        for (int i = 0; i < 4; i++) {
            int kk = bk + 8 * i;
            CPA16(bb + kk * (B_PITCH * 4) + bn16, Xb + (size_t)(k0 + kk) * HW + (bn16 >> 2));
        }
    };

    // prologue: chunks 0 and 1 in flight
    issue_chunk(0, 0);
    CPA_COMMIT();
    issue_chunk(1, STAGE_BYTES);
    CPA_COMMIT();

    int sc_comp = 0;                  // stage byte-offset for chunk c
    int sc_next = 2 * STAGE_BYTES;    // stage byte-offset for chunk c+2

    uint32_t afr[2][4][4];
    uint32_t bfr[2][4][2];

    #pragma unroll 1
    for (int c = 0; c < NCHUNK; c++) {
        CPA_WAIT(1);          // chunk c complete (one group committed per iter)
        __syncthreads();      // data visible; also fences stage reuse

        const uint32_t* Asu = reinterpret_cast<const uint32_t*>(smem + sc_comp);
        const uint32_t* Bsu = reinterpret_cast<const uint32_t*>(smem + sc_comp + A_BYTES);
        const float*    Bsf = reinterpret_cast<const float*>(smem + sc_comp + A_BYTES);

        auto load_frag = [&](int ks, uint32_t a[4][4], uint32_t bf[4][2]) {
            const int k = ks * 8 + tg;
            #pragma unroll
            for (int mf = 0; mf < 4; mf++) {
                int m = wm * 64 + mf * 16 + g;
                a[mf][0] = Asu[m * A_PITCH + k];
                a[mf][1] = Asu[(m + 8) * A_PITCH + k];
                a[mf][2] = Asu[m * A_PITCH + k + 4];
                a[mf][3] = Asu[(m + 8) * A_PITCH + k + 4];
            }
            #pragma unroll
            for (int nf = 0; nf < 4; nf++) {
                int n = wn * 32 + nf * 8 + g;
                if (CVT_FRAG) {
                    bf[nf][0] = f2tf(Bsf[k * B_PITCH + n]);
                    bf[nf][1] = f2tf(Bsf[(k + 4) * B_PITCH + n]);
                } else {
                    bf[nf][0] = Bsu[k * B_PITCH + n];
                    bf[nf][1] = Bsu[(k + 4) * B_PITCH + n];
                }
            }
        };

        load_frag(0, afr[0], bfr[0]);
        #pragma unroll
        for (int ks = 0; ks < 4; ks++) {
            const int cur = ks & 1;
            if (ks < 3) load_frag(ks + 1, afr[cur ^ 1], bfr[cur ^ 1]);
            #pragma unroll
            for (int mf = 0; mf < 4; mf++)
                #pragma unroll
                for (int nf = 0; nf < 4; nf++)
                    mma_tf32(acc[mf][nf], afr[cur][mf], bfr[cur][nf]);
        }

        // issue chunk c+2 (stage freed: everyone passed this iter's barrier)
        if (c + 2 < NCHUNK) issue_chunk(c + 2, sc_next);
        CPA_COMMIT();   // commit every iteration keeps the wait(1) count exact

        sc_comp += STAGE_BYTES; if (sc_comp == 3 * STAGE_BYTES) sc_comp = 0;
        sc_next += STAGE_BYTES; if (sc_next == 3 * STAGE_BYTES) sc_next = 0;
    }
    __syncthreads();

    // epilogue: stage through SMEM, coalesced 16B stores
    float* Cs = reinterpret_cast<float*>(smem);
    #pragma unroll
    for (int half = 0; half < 2; half++) {
        if ((wn >> 1) == half) {
            int cb = wn * 32 - half * 64;
            #pragma unroll
            for (int mf = 0; mf < 4; mf++) {
                #pragma unroll
                for (int nf = 0; nf < 4; nf++) {
                    int row = wm * 64 + mf * 16 + g;
                    int col = cb + nf * 8 + tg * 2;
                    *reinterpret_cast<float2*>(&Cs[row * C_PITCH + col]) =
                        make_float2(acc[mf][nf][0], acc[mf][nf][1]);
                    *reinterpret_cast<float2*>(&Cs[(row + 8) * C_PITCH + col]) =
                        make_float2(acc[mf][nf][2], acc[mf][nf][3]);
                }
            }
        }
        __syncthreads();
        #pragma unroll
        for (int i = 0; i < 8; i++) {
            int r = (t >> 4) + 16 * i;
            int col = (t & 15) * 4;
            float4 v = *reinterpret_cast<const float4*>(&Cs[r * C_PITCH + col]);
            *reinterpret_cast<float4*>(&Cb[(size_t)r * HW + half * 64 + col]) = v;
        }
        __syncthreads();
    }
}

__global__ void __launch_bounds__(256, 2) mma_q_kernel(const float* __restrict__ x) {
    mma_gemm_body<C3, DIM, true>(g_wq, x, g_tq, DIM * HW, 0);
}
__global__ void __launch_bounds__(256, 2) mma_kv_kernel(const float* __restrict__ x) {
    mma_gemm_body<C1, 2 * DIM, true>(g_wkv, x, g_tkv, DIM * HW, C3 * HW);
}
__global__ void __launch_bounds__(256, 2) mma_o_kernel(float* __restrict__ out) {
    mma_gemm_body<DIM, DIM, false>(g_Wc, g_v, out, DIM * HW, 0);
}

// ---------------------------------------------------------------------------
// Fused: dwconv(q) + dwconv(k) + L2 sum-of-squares + 32x32 Gram per head.
// One image row per chunk; 4 rows per block. SMEM ~40 KB -> 4 blocks/SM.
// ---------------------------------------------------------------------------
#define FP      132
#define QC_OFF  0
#define KC_OFF  (32 * FP)            // 4224
#define SG_OFF  (2 * 32 * FP)        // 8448
#define SN_OFF  (SG_OFF + 1024)      // 9472
#define WS_OFF  (SN_OFF + 64)        // 9536
#define FUSED_SMEM_BYTES ((WS_OFF + 576) * 4)   // 40448

__global__ void __launch_bounds__(256, 4) fused_qk_gram_kernel(
        const float* __restrict__ w_qdw, const float* __restrict__ w_kvdw) {
    extern __shared__ float sf[];
    const int h = blockIdx.y, b = blockIdx.z;
    const int t = threadIdx.x;
    const int w = t >> 5, lane = t & 31;
    const int yb = blockIdx.x * 4;

    const float* qbase = g_tq  + ((size_t)b * DIM     + h * HD) * HW;
    const float* kbase = g_tkv + ((size_t)b * 2 * DIM + h * HD) * HW;

    for (int i = t; i < 1024 + 64; i += 256) sf[SG_OFF + i] = 0.f;
    for (int i = t; i < 2 * HD * 9; i += 256) {
        int tens = i / 288, r = i % 288;
        sf[WS_OFF + i] = (tens ? w_kvdw : w_qdw)[(h * HD) * 9 + r];
    }
    __syncthreads();

    float acc[4][4] = {};
    const int seg = t >> 6, tt = t & 63, i4 = tt >> 3, j4 = tt & 7;

    #pragma unroll 1
    for (int ch = 0; ch < 4; ch++) {
        const int oy = yb + ch;
        #pragma unroll 1
        for (int i = 0; i < 8; i++) {
            int task = w + 8 * i;
            int tens = task >> 5;
            int c = task & 31;
            const float* plane = (tens ? kbase : qbase) + (size_t)c * HW;
            float4 r0 = (oy > 0)
                ? *reinterpret_cast<const float4*>(plane + (size_t)(oy - 1) * IMG + lane * 4)
                : make_float4(0.f, 0.f, 0.f, 0.f);
            float4 r1 = *reinterpret_cast<const float4*>(plane + (size_t)oy * IMG + lane * 4);
            float4 r2 = (oy < IMG - 1)
                ? *reinterpret_cast<const float4*>(plane + (size_t)(oy + 1) * IMG + lane * 4)
                : make_float4(0.f, 0.f, 0.f, 0.f);
            float l0 = __shfl_up_sync(0xffffffffu, r0.w, 1);
            float l1 = __shfl_up_sync(0xffffffffu, r1.w, 1);
            float l2 = __shfl_up_sync(0xffffffffu, r2.w, 1);
            float h0 = __shfl_down_sync(0xffffffffu, r0.x, 1);
            float h1 = __shfl_down_sync(0xffffffffu, r1.x, 1);
            float h2 = __shfl_down_sync(0xffffffffu, r2.x, 1);
            if (lane == 0)  { l0 = 0.f; l1 = 0.f; l2 = 0.f; }
            if (lane == 31) { h0 = 0.f; h1 = 0.f; h2 = 0.f; }
            const float* w9 = sf + WS_OFF + tens * 288 + c * 9;
            float wa = w9[0], wb = w9[1], wc = w9[2];
            float wd = w9[3], we = w9[4], wf = w9[5];
            float wg = w9[6], wh = w9[7], wi = w9[8];
            float o0 = wa*l0   + wb*r0.x + wc*r0.y + wd*l1   + we*r1.x + wf*r1.y + wg*l2   + wh*r2.x + wi*r2.y;
            float o1 = wa*r0.x + wb*r0.y + wc*r0.z + wd*r1.x + we*r1.y + wf*r1.z + wg*r2.x + wh*r2.y + wi*r2.z;
            float o2 = wa*r0.y + wb*r0.z + wc*r0.w + wd*r1.y + we*r1.z + wf*r1.w + wg*r2.y + wh*r2.z + wi*r2.w;
            float o3 = wa*r0.z + wb*r0.w + wc*h0   + wd*r1.z + we*r1.w + wf*h1   + wg*r2.z + wh*r2.w + wi*h2;
            *reinterpret_cast<float4*>(sf + (tens ? KC_OFF : QC_OFF) + c * FP + lane * 4) =
                make_float4(o0, o1, o2, o3);
            float ssq = o0*o0 + o1*o1 + o2*o2 + o3*o3;
            #pragma unroll
            for (int off = 16; off > 0; off >>= 1)
                ssq += __shfl_down_sync(0xffffffffu, ssq, off);
            if (lane == 0) atomicAdd(&sf[SN_OFF + tens * HD + c], ssq);
        }
        __syncthreads();
        const float* QCp = sf + QC_OFF;
        const float* KCp = sf + KC_OFF;
        #pragma unroll 2
        for (int jj = seg * 32; jj < seg * 32 + 32; jj += 4) {
            float4 q4[4], k4[4];
            #pragma unroll
            for (int r = 0; r < 4; r++)
                q4[r] = *reinterpret_cast<const float4*>(&QCp[(i4 + 8 * r) * FP + jj]);
            #pragma unroll
            for (int s = 0; s < 4; s++)
                k4[s] = *reinterpret_cast<const float4*>(&KCp[(j4 + 8 * s) * FP + jj]);
            #pragma unroll
            for (int r = 0; r < 4; r++)
                #pragma unroll
                for (int s = 0; s < 4; s++)
                    acc[r][s] += q4[r].x * k4[s].x + q4[r].y * k4[s].y
                               + q4[r].z * k4[s].z + q4[r].w * k4[s].w;
        }
        __syncthreads();
    }
    #pragma unroll
    for (int r = 0; r < 4; r++)
        #pragma unroll
        for (int s = 0; s < 4; s++)
            atomicAdd(&sf[SG_OFF + (i4 + 8 * r) * HD + (j4 + 8 * s)], acc[r][s]);
    __syncthreads();
    float* Gp = g_G + (size_t)(b * HEADS + h) * HD * HD;
    for (int e = t; e < HD * HD; e += 256) atomicAdd(&Gp[e], sf[SG_OFF + e]);
    if (t < 64) {
        float* np = (t < HD) ? g_nq : g_nk;
        atomicAdd(&np[b * DIM + h * HD + (t & 31)], sf[SN_OFF + t]);
    }
}

// ---------------------------------------------------------------------------
// Depthwise 3x3 conv for V (stores tf32 bits for the o-GEMM)
// ---------------------------------------------------------------------------
__global__ void __launch_bounds__(256) dwv_kernel(const float* __restrict__ w9) {
    int b = blockIdx.z, c = blockIdx.y, chunk = blockIdx.x;
    const float* ip = g_tkv + ((size_t)b * 2 * DIM + DIM + c) * HW;
    float*       op = g_v   + ((size_t)b * DIM + c) * HW;
    float wv[9];
    #pragma unroll
    for (int i = 0; i < 9; i++) wv[i] = w9[(DIM + c) * 9 + i];
    #pragma unroll
    for (int it = 0; it < 8; it++) {
        int p = chunk * 2048 + it * 256 + threadIdx.x;
        int y = p >> 7, x = p & 127;
        float s = 0.f;
        #pragma unroll
        for (int dy = -1; dy <= 1; dy++) {
            int yy = y + dy;
            if ((unsigned)yy < (unsigned)IMG) {
                const float* rp = ip + yy * IMG;
                #pragma unroll
                for (int dx = -1; dx <= 1; dx++) {
                    int xx = x + dx;
                    if ((unsigned)xx < (unsigned)IMG)
                        s += wv[(dy + 1) * 3 + dx + 1] * rp[xx];
                }
            }
        }
        op[p] = f2tff(s);
    }
}

// ---------------------------------------------------------------------------
// Softmax + fold attention into w_proj (stores tf32 bits)
// ---------------------------------------------------------------------------
__global__ void __launch_bounds__(256) attn_wc_kernel(const float* __restrict__ temp,
                                                      const float* __restrict__ w_proj) {
    int h = blockIdx.x, b = blockIdx.y;
    int t = threadIdx.x;
    __shared__ float As[HD][HD + 1];
    __shared__ float qn[HD], kn[HD];

    if (t < HD) {
        qn[t] = fmaxf(sqrtf(g_nq[b * DIM + h * HD + t]), 1e-12f);
        kn[t] = fmaxf(sqrtf(g_nk[b * DIM + h * HD + t]), 1e-12f);
    }
    __syncthreads();
    if (t < HD) {
        int c = t;
        float T = temp[h];
        float inq = T / qn[c];
        const float* Gp = &g_G[((size_t)(b * HEADS + h) * HD + c) * HD];
        float rowv[HD];
        float m = -1e30f;
        #pragma unroll
        for (int d = 0; d < HD; d++) {
            float v = Gp[d] * inq / kn[d];
            rowv[d] = v;
            m = fmaxf(m, v);
        }
        float ssum = 0.f;
        #pragma unroll
        for (int d = 0; d < HD; d++) { rowv[d] = expf(rowv[d] - m); ssum += rowv[d]; }
        float inv = 1.f / ssum;
        #pragma unroll
        for (int d = 0; d < HD; d++) As[c][d] = rowv[d] * inv;
    }
    __syncthreads();

    int o = t;
    float wp[HD];
    #pragma unroll
    for (int c = 0; c < HD; c++) wp[c] = w_proj[o * DIM + h * HD + c];
    #pragma unroll 4
    for (int d = 0; d < HD; d++) {
        float s = 0.f;
        #pragma unroll
        for (int c = 0; c < HD; c++) s += wp[c] * As[c][d];
        g_Wc[((size_t)b * DIM + o) * DIM + h * HD + d] = f2tff(s);
    }
}

// ---------------------------------------------------------------------------
// Launch
// ---------------------------------------------------------------------------
extern "C" void kernel_launch(void* const* d_in, const int* in_sizes, int n_in,
                              void* d_out, int out_size) {
    const float* x      = (const float*)d_in[0];
    const float* k_v    = (const float*)d_in[1];
    const float* temper = (const float*)d_in[2];
    const float* w_kR   = (const float*)d_in[3];
    const float* w_kI   = (const float*)d_in[4];
    const float* w_qR   = (const float*)d_in[5];
    const float* w_qdw  = (const float*)d_in[6];
    const float* w_kvI  = (const float*)d_in[7];
    const float* w_kvdw = (const float*)d_in[8];
    const float* w_proj = (const float*)d_in[9];
    float* out = (float*)d_out;

    cudaFuncSetAttribute(mma_q_kernel,  cudaFuncAttributeMaxDynamicSharedMemorySize, SMEM_TOTAL);
    cudaFuncSetAttribute(mma_kv_kernel, cudaFuncAttributeMaxDynamicSharedMemorySize, SMEM_TOTAL);
    cudaFuncSetAttribute(mma_o_kernel,  cudaFuncAttributeMaxDynamicSharedMemorySize, SMEM_TOTAL);
    cudaFuncSetAttribute(fused_qk_gram_kernel, cudaFuncAttributeMaxDynamicSharedMemorySize, FUSED_SMEM_BYTES);

    modk_kernel<<<BATCH, 256>>>(k_v, w_kR, w_kI, w_qR, w_kvI);
    mma_q_kernel <<<dim3(HW / 128, DIM / 128,     BATCH), 256, SMEM_TOTAL>>>(x);
    mma_kv_kernel<<<dim3(HW / 128, 2 * DIM / 128, BATCH), 256, SMEM_TOTAL>>>(x);
    fused_qk_gram_kernel<<<dim3(32, HEADS, BATCH), 256, FUSED_SMEM_BYTES>>>(w_qdw, w_kvdw);
    dwv_kernel<<<dim3(8, DIM, BATCH), 256>>>(w_kvdw);
    attn_wc_kernel<<<dim3(HEADS, BATCH), 256>>>(temper, w_proj);
    mma_o_kernel<<<dim3(HW / 128, DIM / 128, BATCH), 256, SMEM_TOTAL>>>(out);
}

// round 15
// speedup vs baseline: 1.5746x; 1.1258x over previous
#include <cuda_runtime.h>
#include <cuda_fp16.h>
#include <math.h>
#include <stdint.h>

// Problem constants
#define BATCH 4
#define DIM   256
#define C3    192
#define C1    64
#define HEADS 8
#define HD    32
#define HW    16384   // 128*128
#define IMG   128

// ---------------------------------------------------------------------------
// Device scratch
// ---------------------------------------------------------------------------
__device__ __half g_xh  [BATCH * DIM * HW];      // x in half
__device__ __half g_wqh [BATCH * DIM * C3];      // FiLM-folded q weights (half)
__device__ __half g_wkvh[BATCH * 2*DIM * C1];    // FiLM-folded kv weights (half)
__device__ __half g_vh  [BATCH * DIM * HW];      // v post-dwconv (half)
__device__ __half g_Wch [BATCH * DIM * DIM];     // w_proj @ blockdiag(attn) (half)
__device__ float  g_tq  [BATCH * DIM * HW];      // q pre-dwconv (fp32)
__device__ float  g_tkv [BATCH * 2*DIM * HW];    // kv pre-dwconv (fp32)
__device__ float  g_nq  [BATCH * DIM];
__device__ float  g_nk  [BATCH * DIM];
__device__ float  g_G   [BATCH * HEADS * HD * HD];

// ---------------------------------------------------------------------------
// Helpers
// ---------------------------------------------------------------------------
__device__ __forceinline__ uint32_t smem_u32(const void* p) {
    uint32_t a;
    asm("{ .reg .u64 t; cvta.to.shared.u64 t, %1; cvt.u32.u64 %0, t; }" : "=r"(a) : "l"(p));
    return a;
}
#define CPA16(dst, src) asm volatile("cp.async.cg.shared.global [%0], [%1], 16;" :: "r"(dst), "l"(src) : "memory")
#define CPA_COMMIT()    asm volatile("cp.async.commit_group;" ::: "memory")
#define CPA_WAIT(n)     asm volatile("cp.async.wait_group %0;" :: "n"(n) : "memory")

#define LDSM_X4(r, addr) \
    asm volatile("ldmatrix.sync.aligned.m8n8.x4.shared.b16 {%0,%1,%2,%3}, [%4];" \
        : "=r"((r)[0]), "=r"((r)[1]), "=r"((r)[2]), "=r"((r)[3]) : "r"(addr))
#define LDSM_X4_T(r, addr) \
    asm volatile("ldmatrix.sync.aligned.m8n8.x4.trans.shared.b16 {%0,%1,%2,%3}, [%4];" \
        : "=r"((r)[0]), "=r"((r)[1]), "=r"((r)[2]), "=r"((r)[3]) : "r"(addr))

__device__ __forceinline__ void mma_f16(float* c, const uint32_t* a, const uint32_t* b) {
    asm volatile(
        "mma.sync.aligned.m16n8k16.row.col.f32.f16.f16.f32 "
        "{%0,%1,%2,%3}, {%4,%5,%6,%7}, {%8,%9}, {%0,%1,%2,%3};"
        : "+f"(c[0]), "+f"(c[1]), "+f"(c[2]), "+f"(c[3])
        : "r"(a[0]), "r"(a[1]), "r"(a[2]), "r"(a[3]), "r"(b[0]), "r"(b[1]));
}

// GEMM SMEM layout (bytes):
// A stage: 128 rows x 80B  (32 halfs + pad; conflict-free LDSM at pitch 20 words)
// B stage:  32 rows x 272B (128 halfs + pad; conflict-free LDSM at pitch 68 words)
#define A_ROWB   80
#define B_ROWB   272
#define A_STAGE  (128 * A_ROWB)               // 10240
#define B_STAGE  (32 * B_ROWB)                // 8704
#define STAGE    (A_STAGE + B_STAGE)          // 18944
#define SMEM_TOTAL (3 * STAGE)                // 56832
#define C_PITCH  68

// ---------------------------------------------------------------------------
// x -> half conversion (one pass; every GEMM B-fill becomes pure cp.async)
// ---------------------------------------------------------------------------
__global__ void __launch_bounds__(256) cvt_x_kernel(const float* __restrict__ x) {
    size_t i = ((size_t)blockIdx.x * 256 + threadIdx.x) * 8;
    float4 v0 = *reinterpret_cast<const float4*>(x + i);
    float4 v1 = *reinterpret_cast<const float4*>(x + i + 4);
    __half2 h[4];
    h[0] = __floats2half2_rn(v0.x, v0.y);
    h[1] = __floats2half2_rn(v0.z, v0.w);
    h[2] = __floats2half2_rn(v1.x, v1.y);
    h[3] = __floats2half2_rn(v1.z, v1.w);
    *reinterpret_cast<uint4*>(g_xh + i) = *reinterpret_cast<const uint4*>(h);
}

// ---------------------------------------------------------------------------
// FiLM folded into per-batch weights (emitted as half) + zeroing
// ---------------------------------------------------------------------------
__global__ void modk_kernel(const float* __restrict__ k_v,
                            const float* __restrict__ w_kR,
                            const float* __restrict__ w_kI,
                            const float* __restrict__ w_qR,
                            const float* __restrict__ w_kvI) {
    int b = blockIdx.x;
    int t = threadIdx.x;
    __shared__ float sc[DIM];
    if (t < C3) {
        float s = 0.f;
        const float* kb = k_v + b * 256;
        for (int i = 0; i < 192; i++) s += kb[i] * w_kR[t * 192 + i];
        sc[t] = 1.f + s;
    } else {
        int o = t - C3;
        float s = 0.f;
        const float* kb = k_v + b * 256 + 192;
        for (int i = 0; i < 64; i++) s += kb[i] * w_kI[o * 64 + i];
        sc[t] = 1.f + s;
    }
    __syncthreads();
    for (int idx = t; idx < DIM * C3; idx += blockDim.x)
        g_wqh[b * DIM * C3 + idx] = __float2half_rn(w_qR[idx] * sc[idx % C3]);
    for (int idx = t; idx < 2 * DIM * C1; idx += blockDim.x)
        g_wkvh[b * 2 * DIM * C1 + idx] = __float2half_rn(w_kvI[idx] * sc[C3 + (idx & 63)]);
    for (int i = t; i < DIM; i += blockDim.x) {
        g_nq[b * DIM + i] = 0.f;
        g_nk[b * DIM + i] = 0.f;
    }
    for (int i = t; i < HEADS * HD * HD; i += blockDim.x)
        g_G[b * HEADS * HD * HD + i] = 0.f;
}

// ---------------------------------------------------------------------------
// fp16 mma.sync (m16n8k16) GEMM, 3-stage cp.async, ldmatrix operand loads.
// C[b][o][n] = sum_k W[b][o][k] * X[b*xbs + xoff + k][n]; C in fp32.
// Block 128x128, 8 warps (2Mx4N), warp tile 64x32.
// ---------------------------------------------------------------------------
template <int K, int OC>
__device__ __forceinline__ void mma_gemm_body(const __half* __restrict__ W,
                                              const __half* __restrict__ X,
                                              float* __restrict__ C,
                                              int x_bstride, int x_off) {
    extern __shared__ char smem[];
    const int b  = blockIdx.z;
    const int n0 = blockIdx.x * 128;
    const int o0 = blockIdx.y * 128;
    const __half* Wb = W + (size_t)b * OC * K + (size_t)o0 * K;
    const __half* Xb = X + (size_t)b * x_bstride + x_off + n0;
    float*        Cb = C + (size_t)b * OC * HW + (size_t)o0 * HW + n0;

    const int t = threadIdx.x;
    const int warp = t >> 5, lane = t & 31;
    const int wm = warp >> 2, wn = warp & 3;
    const int g = lane >> 2, tg = lane & 3;
    const uint32_t sbase = smem_u32(smem);

    const int lrow = lane & 15;          // ldmatrix row-within-tile
    const int lcol = (lane >> 4) * 16;   // ldmatrix 16B col offset (k8 / n8)

    float acc[4][4][4];
    #pragma unroll
    for (int i = 0; i < 4; i++)
        #pragma unroll
        for (int j = 0; j < 4; j++)
            #pragma unroll
            for (int r = 0; r < 4; r++) acc[i][j][r] = 0.f;

    constexpr int NCHUNK = K / 32;

    auto issue_chunk = [&](int c, uint32_t soff) {
        const int k0 = c * 32;
        uint32_t Ast = sbase + soff;
        uint32_t Bst = Ast + A_STAGE;
        #pragma unroll
        for (int i = 0; i < 2; i++) {       // A: 128 rows x 64B = 512 x 16B
            int task = t + 256 * i;
            int o = task >> 2, q = task & 3;
            CPA16(Ast + o * A_ROWB + q * 16, Wb + (size_t)o * K + k0 + q * 8);
        }
        #pragma unroll
        for (int i = 0; i < 2; i++) {       // B: 32 rows x 256B = 512 x 16B
            int task = t + 256 * i;
            int k = task >> 4, s = task & 15;
            CPA16(Bst + k * B_ROWB + s * 16, Xb + (size_t)(k0 + k) * HW + s * 8);
        }
    };

    issue_chunk(0, 0);      CPA_COMMIT();
    issue_chunk(1, STAGE);  CPA_COMMIT();
    int sc_comp = 0, sc_next = 2 * STAGE;

    #pragma unroll 1
    for (int c = 0; c < NCHUNK; c++) {
        CPA_WAIT(1);          // chunk c complete (one commit per iteration)
        __syncthreads();

        const uint32_t Ast = sbase + sc_comp;
        const uint32_t Bst = Ast + A_STAGE;

        #pragma unroll
        for (int ks = 0; ks < 2; ks++) {
            uint32_t a[4][4], bmat[2][4];
            #pragma unroll
            for (int mf = 0; mf < 4; mf++) {
                uint32_t addr = Ast + (wm * 64 + mf * 16 + lrow) * A_ROWB + lcol + ks * 32;
                LDSM_X4(a[mf], addr);
            }
            #pragma unroll
            for (int np = 0; np < 2; np++) {
                uint32_t addr = Bst + (ks * 16 + lrow) * B_ROWB + (wn * 32 + np * 16) * 2 + lcol;
                LDSM_X4_T(bmat[np], addr);
            }
            #pragma unroll
            for (int mf = 0; mf < 4; mf++)
                #pragma unroll
                for (int nf = 0; nf < 4; nf++)
                    mma_f16(acc[mf][nf], a[mf], &bmat[nf >> 1][(nf & 1) * 2]);
        }

        if (c + 2 < NCHUNK) issue_chunk(c + 2, sc_next);
        CPA_COMMIT();
        sc_comp += STAGE; if (sc_comp == 3 * STAGE) sc_comp = 0;
        sc_next += STAGE; if (sc_next == 3 * STAGE) sc_next = 0;
    }
    __syncthreads();

    // epilogue: stage fp32 through SMEM, coalesced 16B stores
    float* Cs = reinterpret_cast<float*>(smem);
    #pragma unroll
    for (int half = 0; half < 2; half++) {
        if ((wn >> 1) == half) {
            int cb = wn * 32 - half * 64;
            #pragma unroll
            for (int mf = 0; mf < 4; mf++) {
                #pragma unroll
                for (int nf = 0; nf < 4; nf++) {
                    int row = wm * 64 + mf * 16 + g;
                    int col = cb + nf * 8 + tg * 2;
                    *reinterpret_cast<float2*>(&Cs[row * C_PITCH + col]) =
                        make_float2(acc[mf][nf][0], acc[mf][nf][1]);
                    *reinterpret_cast<float2*>(&Cs[(row + 8) * C_PITCH + col]) =
                        make_float2(acc[mf][nf][2], acc[mf][nf][3]);
                }
            }
        }
        __syncthreads();
        #pragma unroll
        for (int i = 0; i < 8; i++) {
            int r = (t >> 4) + 16 * i;
            int col = (t & 15) * 4;
            float4 v = *reinterpret_cast<const float4*>(&Cs[r * C_PITCH + col]);
            *reinterpret_cast<float4*>(&Cb[(size_t)r * HW + half * 64 + col]) = v;
        }
        __syncthreads();
    }
}

__global__ void __launch_bounds__(256) mma_q_kernel() {
    mma_gemm_body<C3, DIM>(g_wqh, g_xh, g_tq, DIM * HW, 0);
}
__global__ void __launch_bounds__(256) mma_kv_kernel() {
    mma_gemm_body<C1, 2 * DIM>(g_wkvh, g_xh, g_tkv, DIM * HW, C3 * HW);
}
__global__ void __launch_bounds__(256) mma_o_kernel(float* __restrict__ out) {
    mma_gemm_body<DIM, DIM>(g_Wch, g_vh, out, DIM * HW, 0);
}

// ---------------------------------------------------------------------------
// Fused: dwconv(q) + dwconv(k) + L2 sum-of-squares + 32x32 Gram per head.
// ---------------------------------------------------------------------------
#define FP      132
#define QC_OFF  0
#define KC_OFF  (32 * FP)
#define SG_OFF  (2 * 32 * FP)
#define SN_OFF  (SG_OFF + 1024)
#define WS_OFF  (SN_OFF + 64)
#define FUSED_SMEM_BYTES ((WS_OFF + 576) * 4)

__global__ void __launch_bounds__(256, 4) fused_qk_gram_kernel(
        const float* __restrict__ w_qdw, const float* __restrict__ w_kvdw) {
    extern __shared__ float sf[];
    const int h = blockIdx.y, b = blockIdx.z;
    const int t = threadIdx.x;
    const int w = t >> 5, lane = t & 31;
    const int yb = blockIdx.x * 4;

    const float* qbase = g_tq  + ((size_t)b * DIM     + h * HD) * HW;
    const float* kbase = g_tkv + ((size_t)b * 2 * DIM + h * HD) * HW;

    for (int i = t; i < 1024 + 64; i += 256) sf[SG_OFF + i] = 0.f;
    for (int i = t; i < 2 * HD * 9; i += 256) {
        int tens = i / 288, r = i % 288;
        sf[WS_OFF + i] = (tens ? w_kvdw : w_qdw)[(h * HD) * 9 + r];
    }
    __syncthreads();

    float acc[4][4] = {};
    const int seg = t >> 6, tt = t & 63, i4 = tt >> 3, j4 = tt & 7;

    #pragma unroll 1
    for (int ch = 0; ch < 4; ch++) {
        const int oy = yb + ch;
        #pragma unroll 1
        for (int i = 0; i < 8; i++) {
            int task = w + 8 * i;
            int tens = task >> 5;
            int c = task & 31;
            const float* plane = (tens ? kbase : qbase) + (size_t)c * HW;
            float4 r0 = (oy > 0)
                ? *reinterpret_cast<const float4*>(plane + (size_t)(oy - 1) * IMG + lane * 4)
                : make_float4(0.f, 0.f, 0.f, 0.f);
            float4 r1 = *reinterpret_cast<const float4*>(plane + (size_t)oy * IMG + lane * 4);
            float4 r2 = (oy < IMG - 1)
                ? *reinterpret_cast<const float4*>(plane + (size_t)(oy + 1) * IMG + lane * 4)
                : make_float4(0.f, 0.f, 0.f, 0.f);
            float l0 = __shfl_up_sync(0xffffffffu, r0.w, 1);
            float l1 = __shfl_up_sync(0xffffffffu, r1.w, 1);
            float l2 = __shfl_up_sync(0xffffffffu, r2.w, 1);
            float h0 = __shfl_down_sync(0xffffffffu, r0.x, 1);
            float h1 = __shfl_down_sync(0xffffffffu, r1.x, 1);
            float h2 = __shfl_down_sync(0xffffffffu, r2.x, 1);
            if (lane == 0)  { l0 = 0.f; l1 = 0.f; l2 = 0.f; }
            if (lane == 31) { h0 = 0.f; h1 = 0.f; h2 = 0.f; }
            const float* w9 = sf + WS_OFF + tens * 288 + c * 9;
            float wa = w9[0], wb = w9[1], wc = w9[2];
            float wd = w9[3], we = w9[4], wf = w9[5];
            float wg = w9[6], wh = w9[7], wi = w9[8];
            float o0 = wa*l0   + wb*r0.x + wc*r0.y + wd*l1   + we*r1.x + wf*r1.y + wg*l2   + wh*r2.x + wi*r2.y;
            float o1 = wa*r0.x + wb*r0.y + wc*r0.z + wd*r1.x + we*r1.y + wf*r1.z + wg*r2.x + wh*r2.y + wi*r2.z;
            float o2 = wa*r0.y + wb*r0.z + wc*r0.w + wd*r1.y + we*r1.z + wf*r1.w + wg*r2.y + wh*r2.z + wi*r2.w;
            float o3 = wa*r0.z + wb*r0.w + wc*h0   + wd*r1.z + we*r1.w + wf*h1   + wg*r2.z + wh*r2.w + wi*h2;
            *reinterpret_cast<float4*>(sf + (tens ? KC_OFF : QC_OFF) + c * FP + lane * 4) =
                make_float4(o0, o1, o2, o3);
            float ssq = o0*o0 + o1*o1 + o2*o2 + o3*o3;
            #pragma unroll
            for (int off = 16; off > 0; off >>= 1)
                ssq += __shfl_down_sync(0xffffffffu, ssq, off);
            if (lane == 0) atomicAdd(&sf[SN_OFF + tens * HD + c], ssq);
        }
        __syncthreads();
        const float* QCp = sf + QC_OFF;
        const float* KCp = sf + KC_OFF;
        #pragma unroll 2
        for (int jj = seg * 32; jj < seg * 32 + 32; jj += 4) {
            float4 q4[4], k4[4];
            #pragma unroll
            for (int r = 0; r < 4; r++)
                q4[r] = *reinterpret_cast<const float4*>(&QCp[(i4 + 8 * r) * FP + jj]);
            #pragma unroll
            for (int s = 0; s < 4; s++)
                k4[s] = *reinterpret_cast<const float4*>(&KCp[(j4 + 8 * s) * FP + jj]);
            #pragma unroll
            for (int r = 0; r < 4; r++)
                #pragma unroll
                for (int s = 0; s < 4; s++)
                    acc[r][s] += q4[r].x * k4[s].x + q4[r].y * k4[s].y
                               + q4[r].z * k4[s].z + q4[r].w * k4[s].w;
        }
        __syncthreads();
    }
    #pragma unroll
    for (int r = 0; r < 4; r++)
        #pragma unroll
        for (int s = 0; s < 4; s++)
            atomicAdd(&sf[SG_OFF + (i4 + 8 * r) * HD + (j4 + 8 * s)], acc[r][s]);
    __syncthreads();
    float* Gp = g_G + (size_t)(b * HEADS + h) * HD * HD;
    for (int e = t; e < HD * HD; e += 256) atomicAdd(&Gp[e], sf[SG_OFF + e]);
    if (t < 64) {
        float* np = (t < HD) ? g_nq : g_nk;
        atomicAdd(&np[b * DIM + h * HD + (t & 31)], sf[SN_OFF + t]);
    }
}

// ---------------------------------------------------------------------------
// Depthwise 3x3 conv for V -> half (B operand of the o-GEMM)
// ---------------------------------------------------------------------------
__global__ void __launch_bounds__(256) dwv_kernel(const float* __restrict__ w9) {
    int b = blockIdx.z, c = blockIdx.y, chunk = blockIdx.x;
    const float* ip = g_tkv + ((size_t)b * 2 * DIM + DIM + c) * HW;
    __half*      op = g_vh  + ((size_t)b * DIM + c) * HW;
    float wv[9];
    #pragma unroll
    for (int i = 0; i < 9; i++) wv[i] = w9[(DIM + c) * 9 + i];
    #pragma unroll
    for (int it = 0; it < 4; it++) {
        int p = chunk * 2048 + it * 512 + threadIdx.x * 2;
        int y = p >> 7, x0 = p & 127;
        float s2[2];
        #pragma unroll
        for (int j = 0; j < 2; j++) {
            int x = x0 + j;
            float s = 0.f;
            #pragma unroll
            for (int dy = -1; dy <= 1; dy++) {
                int yy = y + dy;
                if ((unsigned)yy < (unsigned)IMG) {
                    const float* rp = ip + yy * IMG;
                    #pragma unroll
                    for (int dx = -1; dx <= 1; dx++) {
                        int xx = x + dx;
                        if ((unsigned)xx < (unsigned)IMG)
                            s += wv[(dy + 1) * 3 + dx + 1] * rp[xx];
                    }
                }
            }
            s2[j] = s;
        }
        *reinterpret_cast<__half2*>(op + p) = __floats2half2_rn(s2[0], s2[1]);
    }
}

// ---------------------------------------------------------------------------
// Softmax + fold attention into w_proj (emitted as half)
// ---------------------------------------------------------------------------
__global__ void __launch_bounds__(256) attn_wc_kernel(const float* __restrict__ temp,
                                                      const float* __restrict__ w_proj) {
    int h = blockIdx.x, b = blockIdx.y;
    int t = threadIdx.x;
    __shared__ float As[HD][HD + 1];
    __shared__ float qn[HD], kn[HD];

    if (t < HD) {
        qn[t] = fmaxf(sqrtf(g_nq[b * DIM + h * HD + t]), 1e-12f);
        kn[t] = fmaxf(sqrtf(g_nk[b * DIM + h * HD + t]), 1e-12f);
    }
    __syncthreads();
    if (t < HD) {
        int c = t;
        float T = temp[h];
        float inq = T / qn[c];
        const float* Gp = &g_G[((size_t)(b * HEADS + h) * HD + c) * HD];
        float rowv[HD];
        float m = -1e30f;
        #pragma unroll
        for (int d = 0; d < HD; d++) {
            float v = Gp[d] * inq / kn[d];
            rowv[d] = v;
            m = fmaxf(m, v);
        }
        float ssum = 0.f;
        #pragma unroll
        for (int d = 0; d < HD; d++) { rowv[d] = expf(rowv[d] - m); ssum += rowv[d]; }
        float inv = 1.f / ssum;
        #pragma unroll
        for (int d = 0; d < HD; d++) As[c][d] = rowv[d] * inv;
    }
    __syncthreads();

    int o = t;
    float wp[HD];
    #pragma unroll
    for (int c = 0; c < HD; c++) wp[c] = w_proj[o * DIM + h * HD + c];
    #pragma unroll 4
    for (int d = 0; d < HD; d++) {
        float s = 0.f;
        #pragma unroll
        for (int c = 0; c < HD; c++) s += wp[c] * As[c][d];
        g_Wch[((size_t)b * DIM + o) * DIM + h * HD + d] = __float2half_rn(s);
    }
}

// ---------------------------------------------------------------------------
// Launch
// ---------------------------------------------------------------------------
extern "C" void kernel_launch(void* const* d_in, const int* in_sizes, int n_in,
                              void* d_out, int out_size) {
    const float* x      = (const float*)d_in[0];
    const float* k_v    = (const float*)d_in[1];
    const float* temper = (const float*)d_in[2];
    const float* w_kR   = (const float*)d_in[3];
    const float* w_kI   = (const float*)d_in[4];
    const float* w_qR   = (const float*)d_in[5];
    const float* w_qdw  = (const float*)d_in[6];
    const float* w_kvI  = (const float*)d_in[7];
    const float* w_kvdw = (const float*)d_in[8];
    const float* w_proj = (const float*)d_in[9];
    float* out = (float*)d_out;

    cudaFuncSetAttribute(mma_q_kernel,  cudaFuncAttributeMaxDynamicSharedMemorySize, SMEM_TOTAL);
    cudaFuncSetAttribute(mma_kv_kernel, cudaFuncAttributeMaxDynamicSharedMemorySize, SMEM_TOTAL);
    cudaFuncSetAttribute(mma_o_kernel,  cudaFuncAttributeMaxDynamicSharedMemorySize, SMEM_TOTAL);
    cudaFuncSetAttribute(fused_qk_gram_kernel, cudaFuncAttributeMaxDynamicSharedMemorySize, FUSED_SMEM_BYTES);

    cvt_x_kernel<<<BATCH * DIM * HW / 2048, 256>>>(x);
    modk_kernel<<<BATCH, 256>>>(k_v, w_kR, w_kI, w_qR, w_kvI);
    mma_q_kernel <<<dim3(HW / 128, DIM / 128,     BATCH), 256, SMEM_TOTAL>>>();
    mma_kv_kernel<<<dim3(HW / 128, 2 * DIM / 128, BATCH), 256, SMEM_TOTAL>>>();
    fused_qk_gram_kernel<<<dim3(32, HEADS, BATCH), 256, FUSED_SMEM_BYTES>>>(w_qdw, w_kvdw);
    dwv_kernel<<<dim3(8, DIM, BATCH), 256>>>(w_kvdw);
    attn_wc_kernel<<<dim3(HEADS, BATCH), 256>>>(temper, w_proj);
    mma_o_kernel<<<dim3(HW / 128, DIM / 128, BATCH), 256, SMEM_TOTAL>>>(out);
}

// round 17
// speedup vs baseline: 1.7062x; 1.0836x over previous
#include <cuda_runtime.h>
#include <cuda_fp16.h>
#include <math.h>
#include <stdint.h>

// Problem constants
#define BATCH 4
#define DIM   256
#define C3    192
#define C1    64
#define HEADS 8
#define HD    32
#define HW    16384   // 128*128
#define IMG   128

// ---------------------------------------------------------------------------
// Device scratch
// ---------------------------------------------------------------------------
__device__ __half g_xh  [BATCH * DIM * HW];      // x in half
__device__ __half g_wqh [BATCH * DIM * C3];      // FiLM-folded q weights (half)
__device__ __half g_wkvh[BATCH * 2*DIM * C1];    // FiLM-folded kv weights (half)
__device__ __half g_tqh [BATCH * DIM * HW];      // q pre-dwconv (half)
__device__ __half g_tkvh[BATCH * 2*DIM * HW];    // kv pre-dwconv (half)
__device__ __half g_vh  [BATCH * DIM * HW];      // v post-dwconv (half)
__device__ __half g_Wch [BATCH * DIM * DIM];     // w_proj @ blockdiag(attn) (half)
__device__ float  g_nq  [BATCH * DIM];
__device__ float  g_nk  [BATCH * DIM];
__device__ float  g_G   [BATCH * HEADS * HD * HD];

// ---------------------------------------------------------------------------
// Helpers
// ---------------------------------------------------------------------------
__device__ __forceinline__ uint32_t smem_u32(const void* p) {
    uint32_t a;
    asm("{ .reg .u64 t; cvta.to.shared.u64 t, %1; cvt.u32.u64 %0, t; }" : "=r"(a) : "l"(p));
    return a;
}
#define CPA16(dst, src) asm volatile("cp.async.cg.shared.global [%0], [%1], 16;" :: "r"(dst), "l"(src) : "memory")
#define CPA_COMMIT()    asm volatile("cp.async.commit_group;" ::: "memory")
#define CPA_WAIT(n)     asm volatile("cp.async.wait_group %0;" :: "n"(n) : "memory")

#define LDSM_X4(r, addr) \
    asm volatile("ldmatrix.sync.aligned.m8n8.x4.shared.b16 {%0,%1,%2,%3}, [%4];" \
        : "=r"((r)[0]), "=r"((r)[1]), "=r"((r)[2]), "=r"((r)[3]) : "r"(addr))
#define LDSM_X4_T(r, addr) \
    asm volatile("ldmatrix.sync.aligned.m8n8.x4.trans.shared.b16 {%0,%1,%2,%3}, [%4];" \
        : "=r"((r)[0]), "=r"((r)[1]), "=r"((r)[2]), "=r"((r)[3]) : "r"(addr))

__device__ __forceinline__ void mma_f16(float* c, const uint32_t* a, const uint32_t* b) {
    asm volatile(
        "mma.sync.aligned.m16n8k16.row.col.f32.f16.f16.f32 "
        "{%0,%1,%2,%3}, {%4,%5,%6,%7}, {%8,%9}, {%0,%1,%2,%3};"
        : "+f"(c[0]), "+f"(c[1]), "+f"(c[2]), "+f"(c[3])
        : "r"(a[0]), "r"(a[1]), "r"(a[2]), "r"(a[3]), "r"(b[0]), "r"(b[1]));
}

__device__ __forceinline__ float4 ld_half4(const __half* p) {
    uint2 raw = *reinterpret_cast<const uint2*>(p);
    __half2 h0 = *reinterpret_cast<const __half2*>(&raw.x);
    __half2 h1 = *reinterpret_cast<const __half2*>(&raw.y);
    float2 a = __half22float2(h0), b = __half22float2(h1);
    return make_float4(a.x, a.y, b.x, b.y);
}

// GEMM SMEM layout (bytes)
#define A_ROWB   80
#define B_ROWB   272
#define A_STAGE  (128 * A_ROWB)               // 10240
#define B_STAGE  (32 * B_ROWB)                // 8704
#define STAGE    (A_STAGE + B_STAGE)          // 18944
#define SMEM_TOTAL (3 * STAGE)                // 56832
#define C_PITCH  68     // fp32 epilogue pitch (floats)
#define CH_PITCH 136    // half epilogue pitch (halfs)

// ---------------------------------------------------------------------------
// x -> half conversion
// ---------------------------------------------------------------------------
__global__ void __launch_bounds__(256) cvt_x_kernel(const float* __restrict__ x) {
    size_t i = ((size_t)blockIdx.x * 256 + threadIdx.x) * 8;
    float4 v0 = *reinterpret_cast<const float4*>(x + i);
    float4 v1 = *reinterpret_cast<const float4*>(x + i + 4);
    __half2 h[4];
    h[0] = __floats2half2_rn(v0.x, v0.y);
    h[1] = __floats2half2_rn(v0.z, v0.w);
    h[2] = __floats2half2_rn(v1.x, v1.y);
    h[3] = __floats2half2_rn(v1.z, v1.w);
    *reinterpret_cast<uint4*>(g_xh + i) = *reinterpret_cast<const uint4*>(h);
}

// ---------------------------------------------------------------------------
// FiLM folded into per-batch weights (half) + zeroing
// ---------------------------------------------------------------------------
__global__ void modk_kernel(const float* __restrict__ k_v,
                            const float* __restrict__ w_kR,
                            const float* __restrict__ w_kI,
                            const float* __restrict__ w_qR,
                            const float* __restrict__ w_kvI) {
    int b = blockIdx.x;
    int t = threadIdx.x;
    __shared__ float sc[DIM];
    if (t < C3) {
        float s = 0.f;
        const float* kb = k_v + b * 256;
        for (int i = 0; i < 192; i++) s += kb[i] * w_kR[t * 192 + i];
        sc[t] = 1.f + s;
    } else {
        int o = t - C3;
        float s = 0.f;
        const float* kb = k_v + b * 256 + 192;
        for (int i = 0; i < 64; i++) s += kb[i] * w_kI[o * 64 + i];
        sc[t] = 1.f + s;
    }
    __syncthreads();
    for (int idx = t; idx < DIM * C3; idx += blockDim.x)
        g_wqh[b * DIM * C3 + idx] = __float2half_rn(w_qR[idx] * sc[idx % C3]);
    for (int idx = t; idx < 2 * DIM * C1; idx += blockDim.x)
        g_wkvh[b * 2 * DIM * C1 + idx] = __float2half_rn(w_kvI[idx] * sc[C3 + (idx & 63)]);
    for (int i = t; i < DIM; i += blockDim.x) {
        g_nq[b * DIM + i] = 0.f;
        g_nk[b * DIM + i] = 0.f;
    }
    for (int i = t; i < HEADS * HD * HD; i += blockDim.x)
        g_G[b * HEADS * HD * HD + i] = 0.f;
}

// ---------------------------------------------------------------------------
// fp16 mma.sync (m16n8k16) GEMM, 3-stage cp.async, ldmatrix operand loads.
// HALF_OUT: emit half (single-pass staged epilogue); else fp32 (two-pass).
// ---------------------------------------------------------------------------
template <int K, int OC, bool HALF_OUT>
__device__ __forceinline__ void mma_gemm_body(const __half* __restrict__ W,
                                              const __half* __restrict__ X,
                                              void* __restrict__ Cvoid,
                                              int x_bstride, int x_off) {
    extern __shared__ char smem[];
    const int b  = blockIdx.z;
    const int n0 = blockIdx.x * 128;
    const int o0 = blockIdx.y * 128;
    const __half* Wb = W + (size_t)b * OC * K + (size_t)o0 * K;
    const __half* Xb = X + (size_t)b * x_bstride + x_off + n0;

    const int t = threadIdx.x;
    const int warp = t >> 5, lane = t & 31;
    const int wm = warp >> 2, wn = warp & 3;
    const int g = lane >> 2, tg = lane & 3;
    const uint32_t sbase = smem_u32(smem);

    const int lrow = lane & 15;
    const int lcol = (lane >> 4) * 16;

    float acc[4][4][4];
    #pragma unroll
    for (int i = 0; i < 4; i++)
        #pragma unroll
        for (int j = 0; j < 4; j++)
            #pragma unroll
            for (int r = 0; r < 4; r++) acc[i][j][r] = 0.f;

    constexpr int NCHUNK = K / 32;

    auto issue_chunk = [&](int c, uint32_t soff) {
        const int k0 = c * 32;
        uint32_t Ast = sbase + soff;
        uint32_t Bst = Ast + A_STAGE;
        #pragma unroll
        for (int i = 0; i < 2; i++) {
            int task = t + 256 * i;
            int o = task >> 2, q = task & 3;
            CPA16(Ast + o * A_ROWB + q * 16, Wb + (size_t)o * K + k0 + q * 8);
        }
        #pragma unroll
        for (int i = 0; i < 2; i++) {
            int task = t + 256 * i;
            int k = task >> 4, s = task & 15;
            CPA16(Bst + k * B_ROWB + s * 16, Xb + (size_t)(k0 + k) * HW + s * 8);
        }
    };

    issue_chunk(0, 0);      CPA_COMMIT();
    issue_chunk(1, STAGE);  CPA_COMMIT();
    int sc_comp = 0, sc_next = 2 * STAGE;

    #pragma unroll 1
    for (int c = 0; c < NCHUNK; c++) {
        CPA_WAIT(1);
        __syncthreads();

        const uint32_t Ast = sbase + sc_comp;
        const uint32_t Bst = Ast + A_STAGE;

        #pragma unroll
        for (int ks = 0; ks < 2; ks++) {
            uint32_t a[4][4], bmat[2][4];
            #pragma unroll
            for (int mf = 0; mf < 4; mf++) {
                uint32_t addr = Ast + (wm * 64 + mf * 16 + lrow) * A_ROWB + lcol + ks * 32;
                LDSM_X4(a[mf], addr);
            }
            #pragma unroll
            for (int np = 0; np < 2; np++) {
                uint32_t addr = Bst + (ks * 16 + lrow) * B_ROWB + (wn * 32 + np * 16) * 2 + lcol;
                LDSM_X4_T(bmat[np], addr);
            }
            #pragma unroll
            for (int mf = 0; mf < 4; mf++)
                #pragma unroll
                for (int nf = 0; nf < 4; nf++)
                    mma_f16(acc[mf][nf], a[mf], &bmat[nf >> 1][(nf & 1) * 2]);
        }

        if (c + 2 < NCHUNK) issue_chunk(c + 2, sc_next);
        CPA_COMMIT();
        sc_comp += STAGE; if (sc_comp == 3 * STAGE) sc_comp = 0;
        sc_next += STAGE; if (sc_next == 3 * STAGE) sc_next = 0;
    }
    __syncthreads();

    if (HALF_OUT) {
        // single-pass half epilogue
        __half* Csh = reinterpret_cast<__half*>(smem);
        __half* Cbh = reinterpret_cast<__half*>(Cvoid)
                      + (size_t)b * OC * HW + (size_t)o0 * HW + n0;
        #pragma unroll
        for (int mf = 0; mf < 4; mf++) {
            #pragma unroll
            for (int nf = 0; nf < 4; nf++) {
                int row = wm * 64 + mf * 16 + g;
                int col = wn * 32 + nf * 8 + tg * 2;
                *reinterpret_cast<__half2*>(&Csh[row * CH_PITCH + col]) =
                    __floats2half2_rn(acc[mf][nf][0], acc[mf][nf][1]);
                *reinterpret_cast<__half2*>(&Csh[(row + 8) * CH_PITCH + col]) =
                    __floats2half2_rn(acc[mf][nf][2], acc[mf][nf][3]);
            }
        }
        __syncthreads();
        #pragma unroll
        for (int i = 0; i < 8; i++) {
            int r = (t >> 4) + 16 * i;
            int ch = (t & 15) * 8;
            uint4 v = *reinterpret_cast<const uint4*>(&Csh[r * CH_PITCH + ch]);
            *reinterpret_cast<uint4*>(&Cbh[(size_t)r * HW + ch]) = v;
        }
    } else {
        // two-pass fp32 epilogue
        float* Cs = reinterpret_cast<float*>(smem);
        float* Cb = reinterpret_cast<float*>(Cvoid)
                    + (size_t)b * OC * HW + (size_t)o0 * HW + n0;
        #pragma unroll
        for (int half = 0; half < 2; half++) {
            if ((wn >> 1) == half) {
                int cb = wn * 32 - half * 64;
                #pragma unroll
                for (int mf = 0; mf < 4; mf++) {
                    #pragma unroll
                    for (int nf = 0; nf < 4; nf++) {
                        int row = wm * 64 + mf * 16 + g;
                        int col = cb + nf * 8 + tg * 2;
                        *reinterpret_cast<float2*>(&Cs[row * C_PITCH + col]) =
                            make_float2(acc[mf][nf][0], acc[mf][nf][1]);
                        *reinterpret_cast<float2*>(&Cs[(row + 8) * C_PITCH + col]) =
                            make_float2(acc[mf][nf][2], acc[mf][nf][3]);
                    }
                }
            }
            __syncthreads();
            #pragma unroll
            for (int i = 0; i < 8; i++) {
                int r = (t >> 4) + 16 * i;
                int col = (t & 15) * 4;
                float4 v = *reinterpret_cast<const float4*>(&Cs[r * C_PITCH + col]);
                *reinterpret_cast<float4*>(&Cb[(size_t)r * HW + half * 64 + col]) = v;
            }
            __syncthreads();
        }
    }
}

__global__ void __launch_bounds__(256) mma_q_kernel() {
    mma_gemm_body<C3, DIM, true>(g_wqh, g_xh, g_tqh, DIM * HW, 0);
}
__global__ void __launch_bounds__(256) mma_kv_kernel() {
    mma_gemm_body<C1, 2 * DIM, true>(g_wkvh, g_xh, g_tkvh, DIM * HW, C3 * HW);
}
__global__ void __launch_bounds__(256) mma_o_kernel(float* __restrict__ out) {
    mma_gemm_body<DIM, DIM, false>(g_Wch, g_vh, out, DIM * HW, 0);
}

// ---------------------------------------------------------------------------
// Fused: dwconv(q) + dwconv(k) + L2 sum-of-squares + 32x32 Gram per head.
// Inputs now half (half the DRAM sectors).
// ---------------------------------------------------------------------------
#define FP      132
#define QC_OFF  0
#define KC_OFF  (32 * FP)
#define SG_OFF  (2 * 32 * FP)
#define SN_OFF  (SG_OFF + 1024)
#define WS_OFF  (SN_OFF + 64)
#define FUSED_SMEM_BYTES ((WS_OFF + 576) * 4)

__global__ void __launch_bounds__(256, 4) fused_qk_gram_kernel(
        const float* __restrict__ w_qdw, const float* __restrict__ w_kvdw) {
    extern __shared__ float sf[];
    const int h = blockIdx.y, b = blockIdx.z;
    const int t = threadIdx.x;
    const int w = t >> 5, lane = t & 31;
    const int yb = blockIdx.x * 4;

    const __half* qbase = g_tqh  + ((size_t)b * DIM     + h * HD) * HW;
    const __half* kbase = g_tkvh + ((size_t)b * 2 * DIM + h * HD) * HW;

    for (int i = t; i < 1024 + 64; i += 256) sf[SG_OFF + i] = 0.f;
    for (int i = t; i < 2 * HD * 9; i += 256) {
        int tens = i / 288, r = i % 288;
        sf[WS_OFF + i] = (tens ? w_kvdw : w_qdw)[(h * HD) * 9 + r];
    }
    __syncthreads();

    float acc[4][4] = {};
    const int seg = t >> 6, tt = t & 63, i4 = tt >> 3, j4 = tt & 7;

    #pragma unroll 1
    for (int ch = 0; ch < 4; ch++) {
        const int oy = yb + ch;
        #pragma unroll 1
        for (int i = 0; i < 8; i++) {
            int task = w + 8 * i;
            int tens = task >> 5;
            int c = task & 31;
            const __half* plane = (tens ? kbase : qbase) + (size_t)c * HW;
            float4 r0 = (oy > 0)
                ? ld_half4(plane + (size_t)(oy - 1) * IMG + lane * 4)
                : make_float4(0.f, 0.f, 0.f, 0.f);
            float4 r1 = ld_half4(plane + (size_t)oy * IMG + lane * 4);
            float4 r2 = (oy < IMG - 1)
                ? ld_half4(plane + (size_t)(oy + 1) * IMG + lane * 4)
                : make_float4(0.f, 0.f, 0.f, 0.f);
            float l0 = __shfl_up_sync(0xffffffffu, r0.w, 1);
            float l1 = __shfl_up_sync(0xffffffffu, r1.w, 1);
            float l2 = __shfl_up_sync(0xffffffffu, r2.w, 1);
            float h0 = __shfl_down_sync(0xffffffffu, r0.x, 1);
            float h1 = __shfl_down_sync(0xffffffffu, r1.x, 1);
            float h2 = __shfl_down_sync(0xffffffffu, r2.x, 1);
            if (lane == 0)  { l0 = 0.f; l1 = 0.f; l2 = 0.f; }
            if (lane == 31) { h0 = 0.f; h1 = 0.f; h2 = 0.f; }
            const float* w9 = sf + WS_OFF + tens * 288 + c * 9;
            float wa = w9[0], wb = w9[1], wc = w9[2];
            float wd = w9[3], we = w9[4], wf = w9[5];
            float wg = w9[6], wh = w9[7], wi = w9[8];
            float o0 = wa*l0   + wb*r0.x + wc*r0.y + wd*l1   + we*r1.x + wf*r1.y + wg*l2   + wh*r2.x + wi*r2.y;
            float o1 = wa*r0.x + wb*r0.y + wc*r0.z + wd*r1.x + we*r1.y + wf*r1.z + wg*r2.x + wh*r2.y + wi*r2.z;
            float o2 = wa*r0.y + wb*r0.z + wc*r0.w + wd*r1.y + we*r1.z + wf*r1.w + wg*r2.y + wh*r2.z + wi*r2.w;
            float o3 = wa*r0.z + wb*r0.w + wc*h0   + wd*r1.z + we*r1.w + wf*h1   + wg*r2.z + wh*r2.w + wi*h2;
            *reinterpret_cast<float4*>(sf + (tens ? KC_OFF : QC_OFF) + c * FP + lane * 4) =
                make_float4(o0, o1, o2, o3);
            float ssq = o0*o0 + o1*o1 + o2*o2 + o3*o3;
            #pragma unroll
            for (int off = 16; off > 0; off >>= 1)
                ssq += __shfl_down_sync(0xffffffffu, ssq, off);
            if (lane == 0) atomicAdd(&sf[SN_OFF + tens * HD + c], ssq);
        }
        __syncthreads();
        const float* QCp = sf + QC_OFF;
        const float* KCp = sf + KC_OFF;
        #pragma unroll 2
        for (int jj = seg * 32; jj < seg * 32 + 32; jj += 4) {
            float4 q4[4], k4[4];
            #pragma unroll
            for (int r = 0; r < 4; r++)
                q4[r] = *reinterpret_cast<const float4*>(&QCp[(i4 + 8 * r) * FP + jj]);
            #pragma unroll
            for (int s = 0; s < 4; s++)
                k4[s] = *reinterpret_cast<const float4*>(&KCp[(j4 + 8 * s) * FP + jj]);
            #pragma unroll
            for (int r = 0; r < 4; r++)
                #pragma unroll
                for (int s = 0; s < 4; s++)
                    acc[r][s] += q4[r].x * k4[s].x + q4[r].y * k4[s].y
                               + q4[r].z * k4[s].z + q4[r].w * k4[s].w;
        }
        __syncthreads();
    }
    #pragma unroll
    for (int r = 0; r < 4; r++)
        #pragma unroll
        for (int s = 0; s < 4; s++)
            atomicAdd(&sf[SG_OFF + (i4 + 8 * r) * HD + (j4 + 8 * s)], acc[r][s]);
    __syncthreads();
    float* Gp = g_G + (size_t)(b * HEADS + h) * HD * HD;
    for (int e = t; e < HD * HD; e += 256) atomicAdd(&Gp[e], sf[SG_OFF + e]);
    if (t < 64) {
        float* np = (t < HD) ? g_nq : g_nk;
        atomicAdd(&np[b * DIM + h * HD + (t & 31)], sf[SN_OFF + t]);
    }
}

// ---------------------------------------------------------------------------
// Depthwise 3x3 conv for V: half in -> half out
// ---------------------------------------------------------------------------
__global__ void __launch_bounds__(256) dwv_kernel(const float* __restrict__ w9) {
    int b = blockIdx.z, c = blockIdx.y, chunk = blockIdx.x;
    const __half* ip = g_tkvh + ((size_t)b * 2 * DIM + DIM + c) * HW;
    __half*       op = g_vh   + ((size_t)b * DIM + c) * HW;
    float wv[9];
    #pragma unroll
    for (int i = 0; i < 9; i++) wv[i] = w9[(DIM + c) * 9 + i];
    #pragma unroll
    for (int it = 0; it < 4; it++) {
        int p = chunk * 2048 + it * 512 + threadIdx.x * 2;
        int y = p >> 7, x0 = p & 127;
        float s2[2];
        #pragma unroll
        for (int j = 0; j < 2; j++) {
            int x = x0 + j;
            float s = 0.f;
            #pragma unroll
            for (int dy = -1; dy <= 1; dy++) {
                int yy = y + dy;
                if ((unsigned)yy < (unsigned)IMG) {
                    const __half* rp = ip + yy * IMG;
                    #pragma unroll
                    for (int dx = -1; dx <= 1; dx++) {
                        int xx = x + dx;
                        if ((unsigned)xx < (unsigned)IMG)
                            s += wv[(dy + 1) * 3 + dx + 1] * __half2float(rp[xx]);
                    }
                }
            }
            s2[j] = s;
        }
        *reinterpret_cast<__half2*>(op + p) = __floats2half2_rn(s2[0], s2[1]);
    }
}

// ---------------------------------------------------------------------------
// Softmax + fold attention into w_proj (half)
// ---------------------------------------------------------------------------
__global__ void __launch_bounds__(256) attn_wc_kernel(const float* __restrict__ temp,
                                                      const float* __restrict__ w_proj) {
    int h = blockIdx.x, b = blockIdx.y;
    int t = threadIdx.x;
    __shared__ float As[HD][HD + 1];
    __shared__ float qn[HD], kn[HD];

    if (t < HD) {
        qn[t] = fmaxf(sqrtf(g_nq[b * DIM + h * HD + t]), 1e-12f);
        kn[t] = fmaxf(sqrtf(g_nk[b * DIM + h * HD + t]), 1e-12f);
    }
    __syncthreads();
    if (t < HD) {
        int c = t;
        float T = temp[h];
        float inq = T / qn[c];
        const float* Gp = &g_G[((size_t)(b * HEADS + h) * HD + c) * HD];
        float rowv[HD];
        float m = -1e30f;
        #pragma unroll
        for (int d = 0; d < HD; d++) {
            float v = Gp[d] * inq / kn[d];
            rowv[d] = v;
            m = fmaxf(m, v);
        }
        float ssum = 0.f;
        #pragma unroll
        for (int d = 0; d < HD; d++) { rowv[d] = expf(rowv[d] - m); ssum += rowv[d]; }
        float inv = 1.f / ssum;
        #pragma unroll
        for (int d = 0; d < HD; d++) As[c][d] = rowv[d] * inv;
    }
    __syncthreads();

    int o = t;
    float wp[HD];
    #pragma unroll
    for (int c = 0; c < HD; c++) wp[c] = w_proj[o * DIM + h * HD + c];
    #pragma unroll 4
    for (int d = 0; d < HD; d++) {
        float s = 0.f;
        #pragma unroll
        for (int c = 0; c < HD; c++) s += wp[c] * As[c][d];
        g_Wch[((size_t)b * DIM + o) * DIM + h * HD + d] = __float2half_rn(s);
    }
}

// ---------------------------------------------------------------------------
// Launch
// ---------------------------------------------------------------------------
extern "C" void kernel_launch(void* const* d_in, const int* in_sizes, int n_in,
                              void* d_out, int out_size) {
    const float* x      = (const float*)d_in[0];
    const float* k_v    = (const float*)d_in[1];
    const float* temper = (const float*)d_in[2];
    const float* w_kR   = (const float*)d_in[3];
    const float* w_kI   = (const float*)d_in[4];
    const float* w_qR   = (const float*)d_in[5];
    const float* w_qdw  = (const float*)d_in[6];
    const float* w_kvI  = (const float*)d_in[7];
    const float* w_kvdw = (const float*)d_in[8];
    const float* w_proj = (const float*)d_in[9];
    float* out = (float*)d_out;

    cudaFuncSetAttribute(mma_q_kernel,  cudaFuncAttributeMaxDynamicSharedMemorySize, SMEM_TOTAL);
    cudaFuncSetAttribute(mma_kv_kernel, cudaFuncAttributeMaxDynamicSharedMemorySize, SMEM_TOTAL);
    cudaFuncSetAttribute(mma_o_kernel,  cudaFuncAttributeMaxDynamicSharedMemorySize, SMEM_TOTAL);
    cudaFuncSetAttribute(fused_qk_gram_kernel, cudaFuncAttributeMaxDynamicSharedMemorySize, FUSED_SMEM_BYTES);

    cvt_x_kernel<<<BATCH * DIM * HW / 2048, 256>>>(x);
    modk_kernel<<<BATCH, 256>>>(k_v, w_kR, w_kI, w_qR, w_kvI);
    mma_q_kernel <<<dim3(HW / 128, DIM / 128,     BATCH), 256, SMEM_TOTAL>>>();
    mma_kv_kernel<<<dim3(HW / 128, 2 * DIM / 128, BATCH), 256, SMEM_TOTAL>>>();
    fused_qk_gram_kernel<<<dim3(32, HEADS, BATCH), 256, FUSED_SMEM_BYTES>>>(w_qdw, w_kvdw);
    dwv_kernel<<<dim3(8, DIM, BATCH), 256>>>(w_kvdw);
    attn_wc_kernel<<<dim3(HEADS, BATCH), 256>>>(temper, w_proj);
    mma_o_kernel<<<dim3(HW / 128, DIM / 128, BATCH), 256, SMEM_TOTAL>>>(out);
}